// round 9
// baseline (speedup 1.0000x reference)
#include <cuda_runtime.h>
#include <cuda_bf16.h>

// ---------------- problem constants ----------------
#define MTOK  4096          // B*S tokens
#define DMOD  2048
#define NH    16
#define DH    128
#define SEQ   2048
#define NB    2
#define QSCALE 0.08838834764831845f   // 1/sqrt(128)

typedef unsigned int u32;
typedef __nv_bfloat16  bf16;
typedef __nv_bfloat162 bf162;

// ---------------- scratch (device globals; no allocation allowed) --------
__device__ unsigned short g_xh [MTOK*DMOD], g_xl [MTOK*DMOD];
__device__ unsigned short g_WqTh[DMOD*DMOD], g_WqTl[DMOD*DMOD];
__device__ unsigned short g_WkTh[DH*DMOD],   g_WkTl[DH*DMOD];
__device__ unsigned short g_WvTh[DH*DMOD],   g_WvTl[DH*DMOD];
__device__ unsigned short g_WoTh[DMOD*DMOD], g_WoTl[DMOD*DMOD];
__device__ unsigned short g_Qh [MTOK*DMOD], g_Ql [MTOK*DMOD];
__device__ unsigned short g_Kh [MTOK*DH],   g_Kl [MTOK*DH];
__device__ unsigned short g_Vth[NB*DH*SEQ], g_Vtl[NB*DH*SEQ];
__device__ unsigned short g_AOh[MTOK*DMOD], g_AOl[MTOK*DMOD];

// ---------------- helpers ----------------
__device__ __forceinline__ void mma_bf16(float* c, const u32* a, const u32* b) {
    asm("mma.sync.aligned.m16n8k16.row.col.f32.bf16.bf16.f32 "
        "{%0,%1,%2,%3},{%4,%5,%6,%7},{%8,%9},{%0,%1,%2,%3};"
        : "+f"(c[0]), "+f"(c[1]), "+f"(c[2]), "+f"(c[3])
        : "r"(a[0]), "r"(a[1]), "r"(a[2]), "r"(a[3]), "r"(b[0]), "r"(b[1]));
}

__device__ __forceinline__ u32 packbf(float a, float b) {   // a -> low 16 bits
    bf162 t = __floats2bfloat162_rn(a, b);
    return *reinterpret_cast<u32*>(&t);
}

// ---------------- converters ----------------
// x fp32 -> hi/lo bf16 (elementwise)
__global__ void split_f32(const float* __restrict__ in,
                          unsigned short* __restrict__ h,
                          unsigned short* __restrict__ l, int n4) {
    int i = blockIdx.x * blockDim.x + threadIdx.x;
    if (i >= n4) return;
    float4 v = ((const float4*)in)[i];
    float h0 = __bfloat162float(__float2bfloat16(v.x));
    float h1 = __bfloat162float(__float2bfloat16(v.y));
    float h2 = __bfloat162float(__float2bfloat16(v.z));
    float h3 = __bfloat162float(__float2bfloat16(v.w));
    ((u32*)h)[2*i]   = packbf(h0, h1);
    ((u32*)h)[2*i+1] = packbf(h2, h3);
    ((u32*)l)[2*i]   = packbf(v.x - h0, v.y - h1);
    ((u32*)l)[2*i+1] = packbf(v.z - h2, v.w - h3);
}

// W[K][N] fp32 -> WT[N][K] hi/lo bf16 (tiled transpose + split)
__global__ void wtsplit(const float* __restrict__ W,
                        unsigned short* __restrict__ Th,
                        unsigned short* __restrict__ Tl, int K, int N) {
    __shared__ float t[32][33];
    int nt = blockIdx.x * 32, kt = blockIdx.y * 32;
    int tx = threadIdx.x, ty = threadIdx.y;        // (32, 8)
#pragma unroll
    for (int j = 0; j < 4; j++)
        t[ty + 8*j][tx] = W[(size_t)(kt + ty + 8*j) * N + nt + tx];
    __syncthreads();
#pragma unroll
    for (int j = 0; j < 4; j++) {
        float v = t[tx][ty + 8*j];                  // = W[kt+tx][nt+ty+8j]
        float hv = __bfloat162float(__float2bfloat16(v));
        size_t idx = (size_t)(nt + ty + 8*j) * K + kt + tx;
        ((bf16*)Th)[idx] = __float2bfloat16(hv);
        ((bf16*)Tl)[idx] = __float2bfloat16(v - hv);
    }
}

// ---------------- bf16x3 GEMM via mma.sync ----------------
// C[M,N] = (Ah+Al)[M,K] @ (Bh+Bl)^T  + bias   (B given transposed: [N][K])
// MODE 0: write fp32 Cf.  MODE 1: write hi/lo bf16 (x scale).  MODE 2: V-transposed hi/lo.
#define SASTR 40            // padded smem row stride (bf16 elems) -> conflict-free
template<int MODE>
__global__ __launch_bounds__(256)
void gemm3(const unsigned short* __restrict__ Ah_, const unsigned short* __restrict__ Al_,
           const unsigned short* __restrict__ Bh_, const unsigned short* __restrict__ Bl_,
           const float* __restrict__ bias,
           float* __restrict__ Cf,
           unsigned short* __restrict__ Ch_, unsigned short* __restrict__ Cl_,
           int M, int N, int K, float scale)
{
    __shared__ __align__(16) unsigned short sA[2 * 128 * SASTR];
    __shared__ __align__(16) unsigned short sB[2 * 128 * SASTR];
    const int tid  = threadIdx.x;
    const int warp = tid >> 5, lane = tid & 31;
    const int g = lane >> 2, tig = lane & 3;
    const int wm = warp >> 1, wn = warp & 1;            // 4 x 2 warp grid
    const int m0 = blockIdx.y * 128, n0 = blockIdx.x * 128;

    float acc[2][8][4];
#pragma unroll
    for (int i = 0; i < 2; i++)
#pragma unroll
        for (int j = 0; j < 8; j++)
#pragma unroll
            for (int e = 0; e < 4; e++) acc[i][j][e] = 0.f;

    const int lr = tid >> 1, lc = (tid & 1) * 16;       // loader: row, 16-col half

    for (int kt = 0; kt < K; kt += 32) {
        const size_t aoff = (size_t)(m0 + lr) * K + kt + lc;
        const size_t boff = (size_t)(n0 + lr) * K + kt + lc;
        const int sidx = lr * SASTR + lc;
        *(uint4*)&sA[sidx]          = *(const uint4*)(Ah_ + aoff);
        *(uint4*)&sA[sidx + 8]      = *(const uint4*)(Ah_ + aoff + 8);
        *(uint4*)&sA[5120 + sidx]   = *(const uint4*)(Al_ + aoff);
        *(uint4*)&sA[5120 + sidx+8] = *(const uint4*)(Al_ + aoff + 8);
        *(uint4*)&sB[sidx]          = *(const uint4*)(Bh_ + boff);
        *(uint4*)&sB[sidx + 8]      = *(const uint4*)(Bh_ + boff + 8);
        *(uint4*)&sB[5120 + sidx]   = *(const uint4*)(Bl_ + boff);
        *(uint4*)&sB[5120 + sidx+8] = *(const uint4*)(Bl_ + boff + 8);
        __syncthreads();

#pragma unroll
        for (int s = 0; s < 2; s++) {
            u32 af[2][2][4];
#pragma unroll
            for (int hl = 0; hl < 2; hl++)
#pragma unroll
                for (int mf = 0; mf < 2; mf++) {
                    int base = hl*5120 + (wm*32 + mf*16 + g) * SASTR + s*16 + 2*tig;
                    af[hl][mf][0] = *(const u32*)&sA[base];
                    af[hl][mf][1] = *(const u32*)&sA[base + 8*SASTR];
                    af[hl][mf][2] = *(const u32*)&sA[base + 8];
                    af[hl][mf][3] = *(const u32*)&sA[base + 8*SASTR + 8];
                }
#pragma unroll
            for (int nf = 0; nf < 8; nf++) {
                int bb = (wn*64 + nf*8 + g) * SASTR + s*16 + 2*tig;
                u32 bh[2], bl[2];
                bh[0] = *(const u32*)&sB[bb];
                bh[1] = *(const u32*)&sB[bb + 8];
                bl[0] = *(const u32*)&sB[5120 + bb];
                bl[1] = *(const u32*)&sB[5120 + bb + 8];
#pragma unroll
                for (int mf = 0; mf < 2; mf++) {
                    mma_bf16(acc[mf][nf], af[0][mf], bh);   // Ah*Bh
                    mma_bf16(acc[mf][nf], af[0][mf], bl);   // Ah*Bl
                    mma_bf16(acc[mf][nf], af[1][mf], bh);   // Al*Bh
                }
            }
        }
        __syncthreads();
    }

    // ---- epilogue ----
#pragma unroll
    for (int mf = 0; mf < 2; mf++) {
        int r0 = m0 + wm*32 + mf*16 + g;
#pragma unroll
        for (int nf = 0; nf < 8; nf++) {
            int c = n0 + wn*64 + nf*8 + 2*tig;
            float b0 = bias[c], b1 = bias[c + 1];
            float v0 = acc[mf][nf][0] + b0, v1 = acc[mf][nf][1] + b1;
            float v2 = acc[mf][nf][2] + b0, v3 = acc[mf][nf][3] + b1;
            if (MODE == 0) {
                *(float2*)&Cf[(size_t)r0 * N + c]       = make_float2(v0, v1);
                *(float2*)&Cf[(size_t)(r0 + 8) * N + c] = make_float2(v2, v3);
            } else if (MODE == 1) {
                v0 *= scale; v1 *= scale; v2 *= scale; v3 *= scale;
                float h0 = __bfloat162float(__float2bfloat16(v0));
                float h1 = __bfloat162float(__float2bfloat16(v1));
                float h2 = __bfloat162float(__float2bfloat16(v2));
                float h3 = __bfloat162float(__float2bfloat16(v3));
                *(u32*)&Ch_[(size_t)r0 * N + c]       = packbf(h0, h1);
                *(u32*)&Ch_[(size_t)(r0 + 8) * N + c] = packbf(h2, h3);
                *(u32*)&Cl_[(size_t)r0 * N + c]       = packbf(v0 - h0, v1 - h1);
                *(u32*)&Cl_[(size_t)(r0 + 8) * N + c] = packbf(v2 - h2, v3 - h3);
            } else {  // MODE 2 : V transposed  Vt[b][e=c][s] , b = row>>11
                float vv[4] = {v0, v1, v2, v3};
#pragma unroll
                for (int e = 0; e < 4; e++) {
                    int r = (e < 2) ? r0 : r0 + 8;
                    int cc = c + (e & 1);
                    float v = vv[e];
                    float hv = __bfloat162float(__float2bfloat16(v));
                    size_t idx = ((size_t)(r >> 11) * DH + cc) * SEQ + (r & 2047);
                    ((bf16*)Ch_)[idx] = __float2bfloat16(hv);
                    ((bf16*)Cl_)[idx] = __float2bfloat16(v - hv);
                }
            }
        }
    }
}

// ---------------- flash attention, bf16x3 mma ----------------
// block: 128 thr (4 warps), 64 q-rows for one (b,h). K-tile = 64 keys.
#define KSTR 136            // sK row stride (bf16), rows = keys(64), cols = d(128)
#define VSTR 72             // sV row stride,  rows = e(128),  cols = keys(64)
#define SKELEMS (64 * KSTR)     // 8704
#define SVELEMS (128 * VSTR)    // 9216
#define FLASH_SMEM ((2*SKELEMS + 2*SVELEMS) * 2)   // 71680 B

__global__ __launch_bounds__(128)
void flash_mma(const unsigned short* __restrict__ Qh_, const unsigned short* __restrict__ Ql_,
               const unsigned short* __restrict__ Kh_, const unsigned short* __restrict__ Kl_,
               const unsigned short* __restrict__ Vth_, const unsigned short* __restrict__ Vtl_,
               unsigned short* __restrict__ AOh_, unsigned short* __restrict__ AOl_)
{
    extern __shared__ __align__(16) unsigned short sm[];
    unsigned short* sK0 = sm;
    unsigned short* sK1 = sK0 + SKELEMS;
    unsigned short* sV0 = sK1 + SKELEMS;
    unsigned short* sV1 = sV0 + SVELEMS;

    const int tid = threadIdx.x;
    const int w = tid >> 5, lane = tid & 31;
    const int g = lane >> 2, tig = lane & 3;
    const int b = blockIdx.y >> 4, h = blockIdx.y & 15;
    const int qrow = blockIdx.x * 64 + w * 16 + g;

    // ---- Q fragments resident in registers (hi/lo), Q already scaled ----
    u32 qf[2][8][4];
    {
        size_t qb = (size_t)(b * SEQ + qrow) * DMOD + h * DH;
#pragma unroll
        for (int s = 0; s < 8; s++) {
            int col = s * 16 + 2 * tig;
            qf[0][s][0] = *(const u32*)(Qh_ + qb + col);
            qf[0][s][1] = *(const u32*)(Qh_ + qb + 8ull * DMOD + col);
            qf[0][s][2] = *(const u32*)(Qh_ + qb + col + 8);
            qf[0][s][3] = *(const u32*)(Qh_ + qb + 8ull * DMOD + col + 8);
            qf[1][s][0] = *(const u32*)(Ql_ + qb + col);
            qf[1][s][1] = *(const u32*)(Ql_ + qb + 8ull * DMOD + col);
            qf[1][s][2] = *(const u32*)(Ql_ + qb + col + 8);
            qf[1][s][3] = *(const u32*)(Ql_ + qb + 8ull * DMOD + col + 8);
        }
    }

    float pacc[16][4];
#pragma unroll
    for (int i = 0; i < 16; i++)
#pragma unroll
        for (int e = 0; e < 4; e++) pacc[i][e] = 0.f;
    float m0 = -1e30f, m1 = -1e30f, l0 = 0.f, l1 = 0.f;

    for (int t0 = 0; t0 < SEQ; t0 += 64) {
        // ---- stage K (hi/lo) and Vt (hi/lo) tiles ----
#pragma unroll
        for (int i = tid; i < 1024; i += 128) {
            int r = i >> 4, c = (i & 15) * 8;
            size_t go = (size_t)(b * SEQ + t0 + r) * DH + c;
            *(uint4*)&sK0[r * KSTR + c] = *(const uint4*)(Kh_ + go);
            *(uint4*)&sK1[r * KSTR + c] = *(const uint4*)(Kl_ + go);
        }
#pragma unroll
        for (int i = tid; i < 1024; i += 128) {
            int e = i >> 3, c = (i & 7) * 8;
            size_t go = (size_t)(b * DH + e) * SEQ + t0 + c;
            *(uint4*)&sV0[e * VSTR + c] = *(const uint4*)(Vth_ + go);
            *(uint4*)&sV1[e * VSTR + c] = *(const uint4*)(Vtl_ + go);
        }
        __syncthreads();

        // ---- scores S = Q K^T  (m16 x n64, K=128) ----
        float sa[8][4];
#pragma unroll
        for (int nf = 0; nf < 8; nf++)
#pragma unroll
            for (int e = 0; e < 4; e++) sa[nf][e] = 0.f;

#pragma unroll
        for (int s = 0; s < 8; s++) {
#pragma unroll
            for (int nf = 0; nf < 8; nf++) {
                int bb = (nf * 8 + g) * KSTR + s * 16 + 2 * tig;
                u32 bh[2], bl[2];
                bh[0] = *(const u32*)&sK0[bb];
                bh[1] = *(const u32*)&sK0[bb + 8];
                bl[0] = *(const u32*)&sK1[bb];
                bl[1] = *(const u32*)&sK1[bb + 8];
                mma_bf16(sa[nf], qf[0][s], bh);
                mma_bf16(sa[nf], qf[0][s], bl);
                mma_bf16(sa[nf], qf[1][s], bh);
            }
        }

        // ---- online softmax (thread owns rows g and g+8 of its warp tile) ----
        float mx0 = -1e30f, mx1 = -1e30f;
#pragma unroll
        for (int nf = 0; nf < 8; nf++) {
            mx0 = fmaxf(mx0, fmaxf(sa[nf][0], sa[nf][1]));
            mx1 = fmaxf(mx1, fmaxf(sa[nf][2], sa[nf][3]));
        }
        mx0 = fmaxf(mx0, __shfl_xor_sync(0xffffffffu, mx0, 1));
        mx0 = fmaxf(mx0, __shfl_xor_sync(0xffffffffu, mx0, 2));
        mx1 = fmaxf(mx1, __shfl_xor_sync(0xffffffffu, mx1, 1));
        mx1 = fmaxf(mx1, __shfl_xor_sync(0xffffffffu, mx1, 2));
        float nm0 = fmaxf(m0, mx0), nm1 = fmaxf(m1, mx1);
        float corr0 = __expf(m0 - nm0), corr1 = __expf(m1 - nm1);
        m0 = nm0; m1 = nm1;

        u32 aph[4][4], apl[4][4];          // P fragments (hi / lo), 4 k-slices
        float rs0 = 0.f, rs1 = 0.f;
#pragma unroll
        for (int nf = 0; nf < 8; nf++) {
            float p0 = __expf(sa[nf][0] - nm0);
            float p1 = __expf(sa[nf][1] - nm0);
            float p2 = __expf(sa[nf][2] - nm1);
            float p3 = __expf(sa[nf][3] - nm1);
            rs0 += p0 + p1; rs1 += p2 + p3;
            float h0 = __bfloat162float(__float2bfloat16(p0));
            float h1 = __bfloat162float(__float2bfloat16(p1));
            float h2 = __bfloat162float(__float2bfloat16(p2));
            float h3 = __bfloat162float(__float2bfloat16(p3));
            int ks = nf >> 1, pt = (nf & 1) * 2;
            aph[ks][pt]     = packbf(h0, h1);
            aph[ks][pt + 1] = packbf(h2, h3);
            apl[ks][pt]     = packbf(p0 - h0, p1 - h1);
            apl[ks][pt + 1] = packbf(p2 - h2, p3 - h3);
        }
        rs0 += __shfl_xor_sync(0xffffffffu, rs0, 1);
        rs0 += __shfl_xor_sync(0xffffffffu, rs0, 2);
        rs1 += __shfl_xor_sync(0xffffffffu, rs1, 1);
        rs1 += __shfl_xor_sync(0xffffffffu, rs1, 2);
        l0 = l0 * corr0 + rs0;
        l1 = l1 * corr1 + rs1;
#pragma unroll
        for (int nf = 0; nf < 16; nf++) {
            pacc[nf][0] *= corr0; pacc[nf][1] *= corr0;
            pacc[nf][2] *= corr1; pacc[nf][3] *= corr1;
        }

        // ---- pacc += P V  (m16 x n128, K=64) ----
#pragma unroll
        for (int ks = 0; ks < 4; ks++) {
#pragma unroll
            for (int nf = 0; nf < 16; nf++) {
                int bb = (nf * 8 + g) * VSTR + ks * 16 + 2 * tig;
                u32 bh[2], bl[2];
                bh[0] = *(const u32*)&sV0[bb];
                bh[1] = *(const u32*)&sV0[bb + 8];
                bl[0] = *(const u32*)&sV1[bb];
                bl[1] = *(const u32*)&sV1[bb + 8];
                mma_bf16(pacc[nf], aph[ks], bh);
                mma_bf16(pacc[nf], aph[ks], bl);
                mma_bf16(pacc[nf], apl[ks], bh);
            }
        }
        __syncthreads();
    }

    // ---- epilogue: normalize, split hi/lo, write AO bf16 ----
    float inv0 = 1.f / l0, inv1 = 1.f / l1;
    size_t row0 = (size_t)(b * SEQ + qrow) * DMOD + h * DH;
#pragma unroll
    for (int nf = 0; nf < 16; nf++) {
        int c = nf * 8 + 2 * tig;
        float v0 = pacc[nf][0] * inv0, v1 = pacc[nf][1] * inv0;
        float v2 = pacc[nf][2] * inv1, v3 = pacc[nf][3] * inv1;
        float h0 = __bfloat162float(__float2bfloat16(v0));
        float h1 = __bfloat162float(__float2bfloat16(v1));
        float h2 = __bfloat162float(__float2bfloat16(v2));
        float h3 = __bfloat162float(__float2bfloat16(v3));
        *(u32*)(AOh_ + row0 + c)              = packbf(h0, h1);
        *(u32*)(AOh_ + row0 + 8ull*DMOD + c)  = packbf(h2, h3);
        *(u32*)(AOl_ + row0 + c)              = packbf(v0 - h0, v1 - h1);
        *(u32*)(AOl_ + row0 + 8ull*DMOD + c)  = packbf(v2 - h2, v3 - h3);
    }
}

// ---------------- launch ----------------
extern "C" void kernel_launch(void* const* d_in, const int* in_sizes, int n_in,
                              void* d_out, int out_size)
{
    (void)in_sizes; (void)n_in; (void)out_size;
    const float* x  = (const float*)d_in[0];
    const float* Wq = (const float*)d_in[1];
    const float* bq = (const float*)d_in[2];
    const float* Wk = (const float*)d_in[3];
    const float* bk = (const float*)d_in[4];
    const float* Wv = (const float*)d_in[5];
    const float* bv = (const float*)d_in[6];
    const float* Wo = (const float*)d_in[7];
    const float* bo = (const float*)d_in[8];
    float* out = (float*)d_out;

    void *xh,*xl,*wqh,*wql,*wkh,*wkl,*wvh,*wvl,*woh,*wol;
    void *qh,*ql,*kh,*kl,*vth,*vtl,*aoh,*aol;
    cudaGetSymbolAddress(&xh,  g_xh);   cudaGetSymbolAddress(&xl,  g_xl);
    cudaGetSymbolAddress(&wqh, g_WqTh); cudaGetSymbolAddress(&wql, g_WqTl);
    cudaGetSymbolAddress(&wkh, g_WkTh); cudaGetSymbolAddress(&wkl, g_WkTl);
    cudaGetSymbolAddress(&wvh, g_WvTh); cudaGetSymbolAddress(&wvl, g_WvTl);
    cudaGetSymbolAddress(&woh, g_WoTh); cudaGetSymbolAddress(&wol, g_WoTl);
    cudaGetSymbolAddress(&qh,  g_Qh);   cudaGetSymbolAddress(&ql,  g_Ql);
    cudaGetSymbolAddress(&kh,  g_Kh);   cudaGetSymbolAddress(&kl,  g_Kl);
    cudaGetSymbolAddress(&vth, g_Vth);  cudaGetSymbolAddress(&vtl, g_Vtl);
    cudaGetSymbolAddress(&aoh, g_AOh);  cudaGetSymbolAddress(&aol, g_AOl);

    cudaFuncSetAttribute(flash_mma,
                         cudaFuncAttributeMaxDynamicSharedMemorySize, FLASH_SMEM);

    // 0) convert inputs
    int n4 = MTOK * DMOD / 4;
    split_f32<<<(n4 + 255) / 256, 256>>>(x, (unsigned short*)xh, (unsigned short*)xl, n4);
    wtsplit<<<dim3(DMOD/32, DMOD/32), dim3(32, 8)>>>(Wq, (unsigned short*)wqh, (unsigned short*)wql, DMOD, DMOD);
    wtsplit<<<dim3(DH/32,   DMOD/32), dim3(32, 8)>>>(Wk, (unsigned short*)wkh, (unsigned short*)wkl, DMOD, DH);
    wtsplit<<<dim3(DH/32,   DMOD/32), dim3(32, 8)>>>(Wv, (unsigned short*)wvh, (unsigned short*)wvl, DMOD, DH);
    wtsplit<<<dim3(DMOD/32, DMOD/32), dim3(32, 8)>>>(Wo, (unsigned short*)woh, (unsigned short*)wol, DMOD, DMOD);

    // 1) Q = (x Wq + bq) * scale  -> hi/lo bf16
    gemm3<1><<<dim3(DMOD/128, MTOK/128), 256>>>(
        (unsigned short*)xh, (unsigned short*)xl, (unsigned short*)wqh, (unsigned short*)wql,
        bq, nullptr, (unsigned short*)qh, (unsigned short*)ql, MTOK, DMOD, DMOD, QSCALE);
    // 2) K = x Wk + bk -> hi/lo
    gemm3<1><<<dim3(1, MTOK/128), 256>>>(
        (unsigned short*)xh, (unsigned short*)xl, (unsigned short*)wkh, (unsigned short*)wkl,
        bk, nullptr, (unsigned short*)kh, (unsigned short*)kl, MTOK, DH, DMOD, 1.f);
    // 3) V = x Wv + bv -> transposed hi/lo
    gemm3<2><<<dim3(1, MTOK/128), 256>>>(
        (unsigned short*)xh, (unsigned short*)xl, (unsigned short*)wvh, (unsigned short*)wvl,
        bv, nullptr, (unsigned short*)vth, (unsigned short*)vtl, MTOK, DH, DMOD, 1.f);
    // 4) flash attention -> AO hi/lo
    flash_mma<<<dim3(SEQ/64, NB*NH), 128, FLASH_SMEM>>>(
        (unsigned short*)qh, (unsigned short*)ql, (unsigned short*)kh, (unsigned short*)kl,
        (unsigned short*)vth, (unsigned short*)vtl, (unsigned short*)aoh, (unsigned short*)aol);
    // 5) out = AO Wo + bo (fp32)
    gemm3<0><<<dim3(DMOD/128, MTOK/128), 256>>>(
        (unsigned short*)aoh, (unsigned short*)aol, (unsigned short*)woh, (unsigned short*)wol,
        bo, out, nullptr, nullptr, MTOK, DMOD, DMOD, 1.f);
}

// round 10
// speedup vs baseline: 1.2465x; 1.2465x over previous
#include <cuda_runtime.h>
#include <cuda_bf16.h>

// ---------------- problem constants ----------------
#define MTOK  4096
#define DMOD  2048
#define NH    16
#define DH    128
#define SEQ   2048
#define NB    2
#define QSCALE 0.08838834764831845f   // 1/sqrt(128)

typedef unsigned int u32;
typedef unsigned short u16;
typedef __nv_bfloat16  bf16;
typedef __nv_bfloat162 bf162;

// ---------------- scratch (device globals; 16B-aligned for cp.async) ------
__device__ __align__(256) u16 g_xh [MTOK*DMOD], g_xl [MTOK*DMOD];
__device__ __align__(256) u16 g_WqTh[DMOD*DMOD], g_WqTl[DMOD*DMOD];
__device__ __align__(256) u16 g_WkTh[DH*DMOD],   g_WkTl[DH*DMOD];
__device__ __align__(256) u16 g_WvTh[DH*DMOD],   g_WvTl[DH*DMOD];
__device__ __align__(256) u16 g_WoTh[DMOD*DMOD], g_WoTl[DMOD*DMOD];
__device__ __align__(256) u16 g_Qh [MTOK*DMOD], g_Ql [MTOK*DMOD];
__device__ __align__(256) u16 g_Kh [MTOK*DH],   g_Kl [MTOK*DH];
__device__ __align__(256) u16 g_Vh [MTOK*DH],   g_Vl [MTOK*DH];
__device__ __align__(256) u16 g_AOh[MTOK*DMOD], g_AOl[MTOK*DMOD];

// ---------------- PTX helpers ----------------
__device__ __forceinline__ void mma_bf16(float* c, const u32* a, const u32* b) {
    asm("mma.sync.aligned.m16n8k16.row.col.f32.bf16.bf16.f32 "
        "{%0,%1,%2,%3},{%4,%5,%6,%7},{%8,%9},{%0,%1,%2,%3};"
        : "+f"(c[0]), "+f"(c[1]), "+f"(c[2]), "+f"(c[3])
        : "r"(a[0]), "r"(a[1]), "r"(a[2]), "r"(a[3]), "r"(b[0]), "r"(b[1]));
}
__device__ __forceinline__ void ldsm4(u32& r0, u32& r1, u32& r2, u32& r3, u32 a) {
    asm volatile("ldmatrix.sync.aligned.m8n8.x4.shared.b16 {%0,%1,%2,%3},[%4];"
                 : "=r"(r0), "=r"(r1), "=r"(r2), "=r"(r3) : "r"(a));
}
__device__ __forceinline__ void ldsm4t(u32& r0, u32& r1, u32& r2, u32& r3, u32 a) {
    asm volatile("ldmatrix.sync.aligned.m8n8.x4.trans.shared.b16 {%0,%1,%2,%3},[%4];"
                 : "=r"(r0), "=r"(r1), "=r"(r2), "=r"(r3) : "r"(a));
}
__device__ __forceinline__ void cp16(u32 dst, const void* src) {
    asm volatile("cp.async.cg.shared.global [%0], [%1], 16;" :: "r"(dst), "l"(src));
}
__device__ __forceinline__ void cp_commit() { asm volatile("cp.async.commit_group;"); }
__device__ __forceinline__ void cp_wait0()  { asm volatile("cp.async.wait_group 0;"); }
__device__ __forceinline__ void cp_wait1()  { asm volatile("cp.async.wait_group 1;"); }

__device__ __forceinline__ u32 packbf(float a, float b) {   // a -> low 16 bits
    bf162 t = __floats2bfloat162_rn(a, b);
    return *reinterpret_cast<u32*>(&t);
}

// ---------------- converters ----------------
__global__ void split_f32(const float* __restrict__ in,
                          u16* __restrict__ h, u16* __restrict__ l, int n4) {
    int i = blockIdx.x * blockDim.x + threadIdx.x;
    if (i >= n4) return;
    float4 v = ((const float4*)in)[i];
    float h0 = __bfloat162float(__float2bfloat16(v.x));
    float h1 = __bfloat162float(__float2bfloat16(v.y));
    float h2 = __bfloat162float(__float2bfloat16(v.z));
    float h3 = __bfloat162float(__float2bfloat16(v.w));
    ((u32*)h)[2*i]   = packbf(h0, h1);
    ((u32*)h)[2*i+1] = packbf(h2, h3);
    ((u32*)l)[2*i]   = packbf(v.x - h0, v.y - h1);
    ((u32*)l)[2*i+1] = packbf(v.z - h2, v.w - h3);
}

// W[K][N] fp32 -> WT[N][K] hi/lo bf16
__global__ void wtsplit(const float* __restrict__ W,
                        u16* __restrict__ Th, u16* __restrict__ Tl, int K, int N) {
    __shared__ float t[32][33];
    int nt = blockIdx.x * 32, kt = blockIdx.y * 32;
    int tx = threadIdx.x, ty = threadIdx.y;
#pragma unroll
    for (int j = 0; j < 4; j++)
        t[ty + 8*j][tx] = W[(size_t)(kt + ty + 8*j) * N + nt + tx];
    __syncthreads();
#pragma unroll
    for (int j = 0; j < 4; j++) {
        float v = t[tx][ty + 8*j];
        float hv = __bfloat162float(__float2bfloat16(v));
        size_t idx = (size_t)(nt + ty + 8*j) * K + kt + tx;
        ((bf16*)Th)[idx] = __float2bfloat16(hv);
        ((bf16*)Tl)[idx] = __float2bfloat16(v - hv);
    }
}

// ============================================================================
// bf16x3 GEMM core: C[.,N] = (Ah+Al)@(Bh+Bl)^T + bias, 128x128 tile, BK=32,
// 256 thr (4x2 warps), cp.async double-buffered, ldmatrix fragments.
// MODE 0: fp32 out.  MODE 1: (acc+bias)*scale -> hi/lo bf16 out.
// ============================================================================
#define SASTR 40                     // padded smem row stride (shorts) = 80 B
#define GTILE (128 * SASTR)          // 5120 shorts per (hi|lo) tile
#define GSTAGE (2 * GTILE)           // hi+lo = 10240 shorts
#define GEMM_SMEM (4 * GSTAGE * 2)   // A(2 stages)+B(2 stages) = 81920 B

template<int MODE>
__device__ __forceinline__ void gemm_core(
    const u16* __restrict__ Ah_, const u16* __restrict__ Al_,
    const u16* __restrict__ Bh_, const u16* __restrict__ Bl_,
    const float* __restrict__ bias,
    float* __restrict__ Cf, u16* __restrict__ Ch_, u16* __restrict__ Cl_,
    int N, int K, float scale, int m0, int n0, u16* smem)
{
    const int tid  = threadIdx.x;
    const int warp = tid >> 5, lane = tid & 31;
    const int g = lane >> 2, tig = lane & 3;
    const int wm = warp >> 1, wn = warp & 1;

    const u32 sbase  = (u32)__cvta_generic_to_shared(smem);
    const u32 sBbase = sbase + 2 * GSTAGE * 2;   // bytes

    float acc[2][8][4];
#pragma unroll
    for (int i = 0; i < 2; i++)
#pragma unroll
        for (int j = 0; j < 8; j++)
#pragma unroll
            for (int e = 0; e < 4; e++) acc[i][j][e] = 0.f;

    // loader mapping: 2 threads per row, 16 shorts each (2x cp16)
    const int lr = tid >> 1, lc = (tid & 1) * 16;
    const u32 sldoff = (u32)(lr * SASTR + lc) * 2;

    // ldmatrix lane-offsets (bytes)
    const u32 a_lo = (u32)(((lane & 15) * SASTR + ((lane >> 4) << 3)) * 2);
    const u32 b_lo = (u32)(((((lane >> 4) << 3) + (lane & 7)) * SASTR
                            + (((lane >> 3) & 1) << 3)) * 2);

    const int nk = K / 32;
    // ---- prefetch stage 0 ----
    {
        size_t aoff = (size_t)(m0 + lr) * K + lc;
        size_t boff = (size_t)(n0 + lr) * K + lc;
        cp16(sbase + sldoff,                  Ah_ + aoff);
        cp16(sbase + sldoff + 16,             Ah_ + aoff + 8);
        cp16(sbase + GTILE*2 + sldoff,        Al_ + aoff);
        cp16(sbase + GTILE*2 + sldoff + 16,   Al_ + aoff + 8);
        cp16(sBbase + sldoff,                 Bh_ + boff);
        cp16(sBbase + sldoff + 16,            Bh_ + boff + 8);
        cp16(sBbase + GTILE*2 + sldoff,       Bl_ + boff);
        cp16(sBbase + GTILE*2 + sldoff + 16,  Bl_ + boff + 8);
        cp_commit();
    }

    for (int kt = 0; kt < nk; kt++) {
        if (kt + 1 < nk) {
            int st = (kt + 1) & 1;
            size_t aoff = (size_t)(m0 + lr) * K + (kt + 1) * 32 + lc;
            size_t boff = (size_t)(n0 + lr) * K + (kt + 1) * 32 + lc;
            u32 sa = sbase  + st * GSTAGE * 2;
            u32 sb = sBbase + st * GSTAGE * 2;
            cp16(sa + sldoff,                 Ah_ + aoff);
            cp16(sa + sldoff + 16,            Ah_ + aoff + 8);
            cp16(sa + GTILE*2 + sldoff,       Al_ + aoff);
            cp16(sa + GTILE*2 + sldoff + 16,  Al_ + aoff + 8);
            cp16(sb + sldoff,                 Bh_ + boff);
            cp16(sb + sldoff + 16,            Bh_ + boff + 8);
            cp16(sb + GTILE*2 + sldoff,       Bl_ + boff);
            cp16(sb + GTILE*2 + sldoff + 16,  Bl_ + boff + 8);
            cp_commit();
            cp_wait1();
        } else {
            cp_wait0();
        }
        __syncthreads();

        const int st = kt & 1;
        const u32 saS = sbase  + st * GSTAGE * 2;
        const u32 sbS = sBbase + st * GSTAGE * 2;

#pragma unroll
        for (int s = 0; s < 2; s++) {
            u32 af[2][2][4];
#pragma unroll
            for (int hl = 0; hl < 2; hl++)
#pragma unroll
                for (int mf = 0; mf < 2; mf++)
                    ldsm4(af[hl][mf][0], af[hl][mf][1], af[hl][mf][2], af[hl][mf][3],
                          saS + (u32)(hl * GTILE * 2)
                              + (u32)((wm * 32 + mf * 16) * SASTR * 2)
                              + (u32)(s * 32) + a_lo);
#pragma unroll
            for (int np = 0; np < 4; np++) {
                u32 ba = sbS + (u32)((wn * 64 + np * 16) * SASTR * 2)
                             + (u32)(s * 32) + b_lo;
                u32 bh0[2], bh1[2], bl0[2], bl1[2];
                ldsm4(bh0[0], bh0[1], bh1[0], bh1[1], ba);
                ldsm4(bl0[0], bl0[1], bl1[0], bl1[1], ba + (u32)(GTILE * 2));
#pragma unroll
                for (int mf = 0; mf < 2; mf++) {
                    mma_bf16(acc[mf][2*np],   af[0][mf], bh0);
                    mma_bf16(acc[mf][2*np],   af[0][mf], bl0);
                    mma_bf16(acc[mf][2*np],   af[1][mf], bh0);
                    mma_bf16(acc[mf][2*np+1], af[0][mf], bh1);
                    mma_bf16(acc[mf][2*np+1], af[0][mf], bl1);
                    mma_bf16(acc[mf][2*np+1], af[1][mf], bh1);
                }
            }
        }
        __syncthreads();
    }

    // ---- epilogue ----
#pragma unroll
    for (int mf = 0; mf < 2; mf++) {
        int r0 = m0 + wm * 32 + mf * 16 + g;
#pragma unroll
        for (int nf = 0; nf < 8; nf++) {
            int c = n0 + wn * 64 + nf * 8 + 2 * tig;
            float b0 = bias[c], b1 = bias[c + 1];
            float v0 = acc[mf][nf][0] + b0, v1 = acc[mf][nf][1] + b1;
            float v2 = acc[mf][nf][2] + b0, v3 = acc[mf][nf][3] + b1;
            if (MODE == 0) {
                *(float2*)&Cf[(size_t)r0 * N + c]       = make_float2(v0, v1);
                *(float2*)&Cf[(size_t)(r0 + 8) * N + c] = make_float2(v2, v3);
            } else {
                v0 *= scale; v1 *= scale; v2 *= scale; v3 *= scale;
                float h0 = __bfloat162float(__float2bfloat16(v0));
                float h1 = __bfloat162float(__float2bfloat16(v1));
                float h2 = __bfloat162float(__float2bfloat16(v2));
                float h3 = __bfloat162float(__float2bfloat16(v3));
                *(u32*)&Ch_[(size_t)r0 * N + c]       = packbf(h0, h1);
                *(u32*)&Ch_[(size_t)(r0 + 8) * N + c] = packbf(h2, h3);
                *(u32*)&Cl_[(size_t)r0 * N + c]       = packbf(v0 - h0, v1 - h1);
                *(u32*)&Cl_[(size_t)(r0 + 8) * N + c] = packbf(v2 - h2, v3 - h3);
            }
        }
    }
}

// fused Q/K/V projection: grid.x = 18 (0-15: Q tiles, 16: K, 17: V)
__global__ __launch_bounds__(256)
void gemm_qkv(const u16* __restrict__ xh, const u16* __restrict__ xl,
              const u16* __restrict__ wqh, const u16* __restrict__ wql,
              const u16* __restrict__ wkh, const u16* __restrict__ wkl,
              const u16* __restrict__ wvh, const u16* __restrict__ wvl,
              const float* __restrict__ bq, const float* __restrict__ bk,
              const float* __restrict__ bv,
              u16* Qh, u16* Ql, u16* Kh, u16* Kl, u16* Vh, u16* Vl)
{
    extern __shared__ u16 smem[];
    int bx = blockIdx.x, m0 = blockIdx.y * 128;
    if (bx < 16) {
        gemm_core<1>(xh, xl, wqh, wql, bq, nullptr, Qh, Ql,
                     DMOD, DMOD, QSCALE, m0, bx * 128, smem);
    } else if (bx == 16) {
        gemm_core<1>(xh, xl, wkh, wkl, bk, nullptr, Kh, Kl,
                     DH, DMOD, 1.f, m0, 0, smem);
    } else {
        gemm_core<1>(xh, xl, wvh, wvl, bv, nullptr, Vh, Vl,
                     DH, DMOD, 1.f, m0, 0, smem);
    }
}

__global__ __launch_bounds__(256)
void gemm_o(const u16* __restrict__ aoh, const u16* __restrict__ aol,
            const u16* __restrict__ woh, const u16* __restrict__ wol,
            const float* __restrict__ bo, float* __restrict__ out)
{
    extern __shared__ u16 smem[];
    gemm_core<0>(aoh, aol, woh, wol, bo, out, nullptr, nullptr,
                 DMOD, DMOD, 1.f, blockIdx.y * 128, blockIdx.x * 128, smem);
}

// ============================================================================
// flash attention: 128 thr (4 warps), 64 q-rows per block, 64-key tiles,
// cp.async double-buffered K/V (both row-major), ldmatrix (+trans for V).
// ============================================================================
#define KSTR   136                      // 272 B row stride, 16B-aligned
#define FTILE  (64 * KSTR)              // 8704 shorts per tile
#define FSTAGE (4 * FTILE)              // Kh,Kl,Vh,Vl
#define FLASH_SMEM (2 * FSTAGE * 2)     // 139264 B

__global__ __launch_bounds__(128)
void flash_mma(const u16* __restrict__ Qh_, const u16* __restrict__ Ql_,
               const u16* __restrict__ Kh_, const u16* __restrict__ Kl_,
               const u16* __restrict__ Vh_, const u16* __restrict__ Vl_,
               u16* __restrict__ AOh_, u16* __restrict__ AOl_)
{
    extern __shared__ u16 smem[];
    const u32 sbase = (u32)__cvta_generic_to_shared(smem);

    const int tid = threadIdx.x;
    const int w = tid >> 5, lane = tid & 31;
    const int g = lane >> 2, tig = lane & 3;
    const int b = blockIdx.y >> 4, h = blockIdx.y & 15;
    const int qrow = blockIdx.x * 64 + w * 16 + g;

    // ldmatrix lane-offsets (bytes)
    const u32 kb_lo = (u32)(((((lane >> 4) << 3) + (lane & 7)) * KSTR
                             + (((lane >> 3) & 1) << 3)) * 2);
    const u32 vb_lo = (u32)((((((lane >> 3) & 1) << 3) + (lane & 7)) * KSTR
                             + ((lane >> 4) << 3)) * 2);

    // ---- prefetch stage 0 (t0 = 0) ----
    {
        const size_t base = (size_t)(b * SEQ) * DH;
#pragma unroll
        for (int i = tid; i < 1024; i += 128) {
            int r = i >> 4, c = (i & 15) * 8;
            size_t go = base + (size_t)r * DH + c;
            u32 d = sbase + (u32)((r * KSTR + c) * 2);
            cp16(d,                 Kh_ + go);
            cp16(d + FTILE*2,       Kl_ + go);
            cp16(d + 2*FTILE*2,     Vh_ + go);
            cp16(d + 3*FTILE*2,     Vl_ + go);
        }
        cp_commit();
    }

    // ---- Q fragments resident in registers (hi/lo) ----
    u32 qf[2][8][4];
    {
        size_t qb = (size_t)(b * SEQ + qrow) * DMOD + h * DH;
#pragma unroll
        for (int s = 0; s < 8; s++) {
            int col = s * 16 + 2 * tig;
            qf[0][s][0] = *(const u32*)(Qh_ + qb + col);
            qf[0][s][1] = *(const u32*)(Qh_ + qb + 8ull * DMOD + col);
            qf[0][s][2] = *(const u32*)(Qh_ + qb + col + 8);
            qf[0][s][3] = *(const u32*)(Qh_ + qb + 8ull * DMOD + col + 8);
            qf[1][s][0] = *(const u32*)(Ql_ + qb + col);
            qf[1][s][1] = *(const u32*)(Ql_ + qb + 8ull * DMOD + col);
            qf[1][s][2] = *(const u32*)(Ql_ + qb + col + 8);
            qf[1][s][3] = *(const u32*)(Ql_ + qb + 8ull * DMOD + col + 8);
        }
    }

    float pacc[16][4];
#pragma unroll
    for (int i = 0; i < 16; i++)
#pragma unroll
        for (int e = 0; e < 4; e++) pacc[i][e] = 0.f;
    float m0 = -1e30f, m1 = -1e30f, l0 = 0.f, l1 = 0.f;

    const int NT = SEQ / 64;
    for (int it = 0; it < NT; it++) {
        if (it + 1 < NT) {
            int st = (it + 1) & 1;
            const size_t base = (size_t)(b * SEQ + (it + 1) * 64) * DH;
            u32 sst = sbase + (u32)(st * FSTAGE * 2);
#pragma unroll
            for (int i = tid; i < 1024; i += 128) {
                int r = i >> 4, c = (i & 15) * 8;
                size_t go = base + (size_t)r * DH + c;
                u32 d = sst + (u32)((r * KSTR + c) * 2);
                cp16(d,             Kh_ + go);
                cp16(d + FTILE*2,   Kl_ + go);
                cp16(d + 2*FTILE*2, Vh_ + go);
                cp16(d + 3*FTILE*2, Vl_ + go);
            }
            cp_commit();
            cp_wait1();
        } else {
            cp_wait0();
        }
        __syncthreads();

        const u32 sst = sbase + (u32)((it & 1) * FSTAGE * 2);
        const u32 sKh = sst, sKl = sst + FTILE*2;
        const u32 sVh = sst + 2*FTILE*2, sVl = sst + 3*FTILE*2;

        // ---- scores S = Q K^T ----
        float sa[8][4];
#pragma unroll
        for (int nf = 0; nf < 8; nf++)
#pragma unroll
            for (int e = 0; e < 4; e++) sa[nf][e] = 0.f;

#pragma unroll
        for (int s = 0; s < 8; s++) {
#pragma unroll
            for (int np = 0; np < 4; np++) {
                u32 ba = (u32)(np * 16 * KSTR * 2) + (u32)(s * 32) + kb_lo;
                u32 bh0[2], bh1[2], bl0[2], bl1[2];
                ldsm4(bh0[0], bh0[1], bh1[0], bh1[1], sKh + ba);
                ldsm4(bl0[0], bl0[1], bl1[0], bl1[1], sKl + ba);
                mma_bf16(sa[2*np],   qf[0][s], bh0);
                mma_bf16(sa[2*np],   qf[0][s], bl0);
                mma_bf16(sa[2*np],   qf[1][s], bh0);
                mma_bf16(sa[2*np+1], qf[0][s], bh1);
                mma_bf16(sa[2*np+1], qf[0][s], bl1);
                mma_bf16(sa[2*np+1], qf[1][s], bh1);
            }
        }

        // ---- online softmax ----
        float mx0 = -1e30f, mx1 = -1e30f;
#pragma unroll
        for (int nf = 0; nf < 8; nf++) {
            mx0 = fmaxf(mx0, fmaxf(sa[nf][0], sa[nf][1]));
            mx1 = fmaxf(mx1, fmaxf(sa[nf][2], sa[nf][3]));
        }
        mx0 = fmaxf(mx0, __shfl_xor_sync(0xffffffffu, mx0, 1));
        mx0 = fmaxf(mx0, __shfl_xor_sync(0xffffffffu, mx0, 2));
        mx1 = fmaxf(mx1, __shfl_xor_sync(0xffffffffu, mx1, 1));
        mx1 = fmaxf(mx1, __shfl_xor_sync(0xffffffffu, mx1, 2));
        float nm0 = fmaxf(m0, mx0), nm1 = fmaxf(m1, mx1);
        float corr0 = __expf(m0 - nm0), corr1 = __expf(m1 - nm1);
        m0 = nm0; m1 = nm1;

        u32 aph[4][4], apl[4][4];
        float rs0 = 0.f, rs1 = 0.f;
#pragma unroll
        for (int nf = 0; nf < 8; nf++) {
            float p0 = __expf(sa[nf][0] - nm0);
            float p1 = __expf(sa[nf][1] - nm0);
            float p2 = __expf(sa[nf][2] - nm1);
            float p3 = __expf(sa[nf][3] - nm1);
            rs0 += p0 + p1; rs1 += p2 + p3;
            float h0 = __bfloat162float(__float2bfloat16(p0));
            float h1 = __bfloat162float(__float2bfloat16(p1));
            float h2 = __bfloat162float(__float2bfloat16(p2));
            float h3 = __bfloat162float(__float2bfloat16(p3));
            int ks = nf >> 1, pt = (nf & 1) * 2;
            aph[ks][pt]     = packbf(h0, h1);
            aph[ks][pt + 1] = packbf(h2, h3);
            apl[ks][pt]     = packbf(p0 - h0, p1 - h1);
            apl[ks][pt + 1] = packbf(p2 - h2, p3 - h3);
        }
        rs0 += __shfl_xor_sync(0xffffffffu, rs0, 1);
        rs0 += __shfl_xor_sync(0xffffffffu, rs0, 2);
        rs1 += __shfl_xor_sync(0xffffffffu, rs1, 1);
        rs1 += __shfl_xor_sync(0xffffffffu, rs1, 2);
        l0 = l0 * corr0 + rs0;
        l1 = l1 * corr1 + rs1;
#pragma unroll
        for (int nf = 0; nf < 16; nf++) {
            pacc[nf][0] *= corr0; pacc[nf][1] *= corr0;
            pacc[nf][2] *= corr1; pacc[nf][3] *= corr1;
        }

        // ---- pacc += P V (V row-major via ldmatrix.trans) ----
#pragma unroll
        for (int ks = 0; ks < 4; ks++) {
#pragma unroll
            for (int np = 0; np < 8; np++) {
                u32 va = (u32)((ks * 16 * KSTR + np * 16) * 2) + vb_lo;
                u32 bh0[2], bh1[2], bl0[2], bl1[2];
                ldsm4t(bh0[0], bh0[1], bh1[0], bh1[1], sVh + va);
                ldsm4t(bl0[0], bl0[1], bl1[0], bl1[1], sVl + va);
                mma_bf16(pacc[2*np],   aph[ks], bh0);
                mma_bf16(pacc[2*np],   aph[ks], bl0);
                mma_bf16(pacc[2*np],   apl[ks], bh0);
                mma_bf16(pacc[2*np+1], aph[ks], bh1);
                mma_bf16(pacc[2*np+1], aph[ks], bl1);
                mma_bf16(pacc[2*np+1], apl[ks], bh1);
            }
        }
        __syncthreads();
    }

    // ---- epilogue: normalize, split hi/lo, write AO ----
    float inv0 = 1.f / l0, inv1 = 1.f / l1;
    size_t row0 = (size_t)(b * SEQ + qrow) * DMOD + h * DH;
#pragma unroll
    for (int nf = 0; nf < 16; nf++) {
        int c = nf * 8 + 2 * tig;
        float v0 = pacc[nf][0] * inv0, v1 = pacc[nf][1] * inv0;
        float v2 = pacc[nf][2] * inv1, v3 = pacc[nf][3] * inv1;
        float h0 = __bfloat162float(__float2bfloat16(v0));
        float h1 = __bfloat162float(__float2bfloat16(v1));
        float h2 = __bfloat162float(__float2bfloat16(v2));
        float h3 = __bfloat162float(__float2bfloat16(v3));
        *(u32*)(AOh_ + row0 + c)              = packbf(h0, h1);
        *(u32*)(AOh_ + row0 + 8ull*DMOD + c)  = packbf(h2, h3);
        *(u32*)(AOl_ + row0 + c)              = packbf(v0 - h0, v1 - h1);
        *(u32*)(AOl_ + row0 + 8ull*DMOD + c)  = packbf(v2 - h2, v3 - h3);
    }
}

// ---------------- launch ----------------
extern "C" void kernel_launch(void* const* d_in, const int* in_sizes, int n_in,
                              void* d_out, int out_size)
{
    (void)in_sizes; (void)n_in; (void)out_size;
    const float* x  = (const float*)d_in[0];
    const float* Wq = (const float*)d_in[1];
    const float* bq = (const float*)d_in[2];
    const float* Wk = (const float*)d_in[3];
    const float* bk = (const float*)d_in[4];
    const float* Wv = (const float*)d_in[5];
    const float* bv = (const float*)d_in[6];
    const float* Wo = (const float*)d_in[7];
    const float* bo = (const float*)d_in[8];
    float* out = (float*)d_out;

    void *xh,*xl,*wqh,*wql,*wkh,*wkl,*wvh,*wvl,*woh,*wol;
    void *qh,*ql,*kh,*kl,*vh,*vl,*aoh,*aol;
    cudaGetSymbolAddress(&xh,  g_xh);   cudaGetSymbolAddress(&xl,  g_xl);
    cudaGetSymbolAddress(&wqh, g_WqTh); cudaGetSymbolAddress(&wql, g_WqTl);
    cudaGetSymbolAddress(&wkh, g_WkTh); cudaGetSymbolAddress(&wkl, g_WkTl);
    cudaGetSymbolAddress(&wvh, g_WvTh); cudaGetSymbolAddress(&wvl, g_WvTl);
    cudaGetSymbolAddress(&woh, g_WoTh); cudaGetSymbolAddress(&wol, g_WoTl);
    cudaGetSymbolAddress(&qh,  g_Qh);   cudaGetSymbolAddress(&ql,  g_Ql);
    cudaGetSymbolAddress(&kh,  g_Kh);   cudaGetSymbolAddress(&kl,  g_Kl);
    cudaGetSymbolAddress(&vh,  g_Vh);   cudaGetSymbolAddress(&vl,  g_Vl);
    cudaGetSymbolAddress(&aoh, g_AOh);  cudaGetSymbolAddress(&aol, g_AOl);

    cudaFuncSetAttribute(gemm_qkv,
        cudaFuncAttributeMaxDynamicSharedMemorySize, GEMM_SMEM);
    cudaFuncSetAttribute(gemm_o,
        cudaFuncAttributeMaxDynamicSharedMemorySize, GEMM_SMEM);
    cudaFuncSetAttribute(flash_mma,
        cudaFuncAttributeMaxDynamicSharedMemorySize, FLASH_SMEM);

    // 0) split inputs
    int n4 = MTOK * DMOD / 4;
    split_f32<<<(n4 + 255) / 256, 256>>>(x, (u16*)xh, (u16*)xl, n4);
    wtsplit<<<dim3(DMOD/32, DMOD/32), dim3(32, 8)>>>(Wq, (u16*)wqh, (u16*)wql, DMOD, DMOD);
    wtsplit<<<dim3(DH/32,   DMOD/32), dim3(32, 8)>>>(Wk, (u16*)wkh, (u16*)wkl, DMOD, DH);
    wtsplit<<<dim3(DH/32,   DMOD/32), dim3(32, 8)>>>(Wv, (u16*)wvh, (u16*)wvl, DMOD, DH);
    wtsplit<<<dim3(DMOD/32, DMOD/32), dim3(32, 8)>>>(Wo, (u16*)woh, (u16*)wol, DMOD, DMOD);

    // 1) fused Q/K/V projections
    gemm_qkv<<<dim3(18, MTOK/128), 256, GEMM_SMEM>>>(
        (u16*)xh, (u16*)xl, (u16*)wqh, (u16*)wql, (u16*)wkh, (u16*)wkl,
        (u16*)wvh, (u16*)wvl, bq, bk, bv,
        (u16*)qh, (u16*)ql, (u16*)kh, (u16*)kl, (u16*)vh, (u16*)vl);

    // 2) flash attention
    flash_mma<<<dim3(SEQ/64, NB*NH), 128, FLASH_SMEM>>>(
        (u16*)qh, (u16*)ql, (u16*)kh, (u16*)kl, (u16*)vh, (u16*)vl,
        (u16*)aoh, (u16*)aol);

    // 3) out = AO @ Wo + bo (fp32)
    gemm_o<<<dim3(DMOD/128, MTOK/128), 256, GEMM_SMEM>>>(
        (u16*)aoh, (u16*)aol, (u16*)woh, (u16*)wol, bo, out);
}

// round 12
// speedup vs baseline: 1.3429x; 1.0773x over previous
#include <cuda_runtime.h>
#include <cuda_bf16.h>

// ---------------- problem constants ----------------
#define MTOK  4096
#define DMOD  2048
#define NH    16
#define DH    128
#define SEQ   2048
#define NB    2
#define QSCALE 0.08838834764831845f   // 1/sqrt(128)

typedef unsigned int u32;
typedef unsigned short u16;
typedef __nv_bfloat16  bf16;
typedef __nv_bfloat162 bf162;

// ---------------- scratch (device globals; 16B-aligned for cp.async) ------
__device__ __align__(256) u16 g_xh [MTOK*DMOD], g_xl [MTOK*DMOD];
__device__ __align__(256) u16 g_WqTh[DMOD*DMOD], g_WqTl[DMOD*DMOD];
__device__ __align__(256) u16 g_WkTh[DH*DMOD],   g_WkTl[DH*DMOD];
__device__ __align__(256) u16 g_WvTh[DH*DMOD],   g_WvTl[DH*DMOD];
__device__ __align__(256) u16 g_WoTh[DMOD*DMOD], g_WoTl[DMOD*DMOD];
__device__ __align__(256) u16 g_Qh [MTOK*DMOD], g_Ql [MTOK*DMOD];
__device__ __align__(256) u16 g_Kh [MTOK*DH],   g_Kl [MTOK*DH];
__device__ __align__(256) u16 g_Vh [MTOK*DH],   g_Vl [MTOK*DH];
__device__ __align__(256) u16 g_AOh[MTOK*DMOD], g_AOl[MTOK*DMOD];

// ---------------- PTX helpers ----------------
__device__ __forceinline__ void mma_bf16(float* c, const u32* a, const u32* b) {
    asm("mma.sync.aligned.m16n8k16.row.col.f32.bf16.bf16.f32 "
        "{%0,%1,%2,%3},{%4,%5,%6,%7},{%8,%9},{%0,%1,%2,%3};"
        : "+f"(c[0]), "+f"(c[1]), "+f"(c[2]), "+f"(c[3])
        : "r"(a[0]), "r"(a[1]), "r"(a[2]), "r"(a[3]), "r"(b[0]), "r"(b[1]));
}
__device__ __forceinline__ void ldsm4(u32& r0, u32& r1, u32& r2, u32& r3, u32 a) {
    asm volatile("ldmatrix.sync.aligned.m8n8.x4.shared.b16 {%0,%1,%2,%3},[%4];"
                 : "=r"(r0), "=r"(r1), "=r"(r2), "=r"(r3) : "r"(a));
}
__device__ __forceinline__ void ldsm4t(u32& r0, u32& r1, u32& r2, u32& r3, u32 a) {
    asm volatile("ldmatrix.sync.aligned.m8n8.x4.trans.shared.b16 {%0,%1,%2,%3},[%4];"
                 : "=r"(r0), "=r"(r1), "=r"(r2), "=r"(r3) : "r"(a));
}
__device__ __forceinline__ void cp16(u32 dst, const void* src) {
    asm volatile("cp.async.cg.shared.global [%0], [%1], 16;" :: "r"(dst), "l"(src));
}
__device__ __forceinline__ void cp_commit() { asm volatile("cp.async.commit_group;"); }
__device__ __forceinline__ void cp_wait0()  { asm volatile("cp.async.wait_group 0;"); }
__device__ __forceinline__ void cp_wait1()  { asm volatile("cp.async.wait_group 1;"); }

__device__ __forceinline__ u32 packbf(float a, float b) {   // a -> low 16 bits
    bf162 t = __floats2bfloat162_rn(a, b);
    return *reinterpret_cast<u32*>(&t);
}

// ---------------- converters ----------------
__global__ void split_f32(const float* __restrict__ in,
                          u16* __restrict__ h, u16* __restrict__ l, int n4) {
    int i = blockIdx.x * blockDim.x + threadIdx.x;
    if (i >= n4) return;
    float4 v = ((const float4*)in)[i];
    float h0 = __bfloat162float(__float2bfloat16(v.x));
    float h1 = __bfloat162float(__float2bfloat16(v.y));
    float h2 = __bfloat162float(__float2bfloat16(v.z));
    float h3 = __bfloat162float(__float2bfloat16(v.w));
    ((u32*)h)[2*i]   = packbf(h0, h1);
    ((u32*)h)[2*i+1] = packbf(h2, h3);
    ((u32*)l)[2*i]   = packbf(v.x - h0, v.y - h1);
    ((u32*)l)[2*i+1] = packbf(v.z - h2, v.w - h3);
}

// W[K][N] fp32 -> WT[N][K] hi/lo bf16
__global__ void wtsplit(const float* __restrict__ W,
                        u16* __restrict__ Th, u16* __restrict__ Tl, int K, int N) {
    __shared__ float t[32][33];
    int nt = blockIdx.x * 32, kt = blockIdx.y * 32;
    int tx = threadIdx.x, ty = threadIdx.y;
#pragma unroll
    for (int j = 0; j < 4; j++)
        t[ty + 8*j][tx] = W[(size_t)(kt + ty + 8*j) * N + nt + tx];
    __syncthreads();
#pragma unroll
    for (int j = 0; j < 4; j++) {
        float v = t[tx][ty + 8*j];
        float hv = __bfloat162float(__float2bfloat16(v));
        size_t idx = (size_t)(nt + ty + 8*j) * K + kt + tx;
        ((bf16*)Th)[idx] = __float2bfloat16(hv);
        ((bf16*)Tl)[idx] = __float2bfloat16(v - hv);
    }
}

// ============================================================================
// bf16x3 GEMM core: C[.,N] = (Ah+Al)@(Bh+Bl)^T + bias, 128x128 tile, BK=32,
// 256 thr (4x2 warps), cp.async double-buffered, ldmatrix fragments.
// Occupancy 2 CTAs/SM for bubble-filling.
// MODE 0: fp32 out.  MODE 1: (acc+bias)*scale -> hi/lo bf16 out.
// ============================================================================
#define SASTR 40                     // padded smem row stride (shorts) = 80 B
#define GTILE (128 * SASTR)          // 5120 shorts per (hi|lo) tile
#define GSTAGE (2 * GTILE)           // hi+lo = 10240 shorts
#define GEMM_SMEM (4 * GSTAGE * 2)   // A(2 stages)+B(2 stages) = 81920 B

template<int MODE>
__device__ __forceinline__ void gemm_core(
    const u16* __restrict__ Ah_, const u16* __restrict__ Al_,
    const u16* __restrict__ Bh_, const u16* __restrict__ Bl_,
    const float* __restrict__ bias,
    float* __restrict__ Cf, u16* __restrict__ Ch_, u16* __restrict__ Cl_,
    int N, int K, float scale, int m0, int n0, u16* smem)
{
    const int tid  = threadIdx.x;
    const int warp = tid >> 5, lane = tid & 31;
    const int g = lane >> 2, tig = lane & 3;
    const int wm = warp >> 1, wn = warp & 1;

    const u32 sbase  = (u32)__cvta_generic_to_shared(smem);
    const u32 sBbase = sbase + 2 * GSTAGE * 2;   // bytes

    float acc[2][8][4];
#pragma unroll
    for (int i = 0; i < 2; i++)
#pragma unroll
        for (int j = 0; j < 8; j++)
#pragma unroll
            for (int e = 0; e < 4; e++) acc[i][j][e] = 0.f;

    const int lr = tid >> 1, lc = (tid & 1) * 16;
    const u32 sldoff = (u32)(lr * SASTR + lc) * 2;

    const u32 a_lo = (u32)(((lane & 15) * SASTR + ((lane >> 4) << 3)) * 2);
    const u32 b_lo = (u32)(((((lane >> 4) << 3) + (lane & 7)) * SASTR
                            + (((lane >> 3) & 1) << 3)) * 2);

    const int nk = K / 32;
    {
        size_t aoff = (size_t)(m0 + lr) * K + lc;
        size_t boff = (size_t)(n0 + lr) * K + lc;
        cp16(sbase + sldoff,                  Ah_ + aoff);
        cp16(sbase + sldoff + 16,             Ah_ + aoff + 8);
        cp16(sbase + GTILE*2 + sldoff,        Al_ + aoff);
        cp16(sbase + GTILE*2 + sldoff + 16,   Al_ + aoff + 8);
        cp16(sBbase + sldoff,                 Bh_ + boff);
        cp16(sBbase + sldoff + 16,            Bh_ + boff + 8);
        cp16(sBbase + GTILE*2 + sldoff,       Bl_ + boff);
        cp16(sBbase + GTILE*2 + sldoff + 16,  Bl_ + boff + 8);
        cp_commit();
    }

    for (int kt = 0; kt < nk; kt++) {
        if (kt + 1 < nk) {
            int st = (kt + 1) & 1;
            size_t aoff = (size_t)(m0 + lr) * K + (kt + 1) * 32 + lc;
            size_t boff = (size_t)(n0 + lr) * K + (kt + 1) * 32 + lc;
            u32 sa = sbase  + st * GSTAGE * 2;
            u32 sb = sBbase + st * GSTAGE * 2;
            cp16(sa + sldoff,                 Ah_ + aoff);
            cp16(sa + sldoff + 16,            Ah_ + aoff + 8);
            cp16(sa + GTILE*2 + sldoff,       Al_ + aoff);
            cp16(sa + GTILE*2 + sldoff + 16,  Al_ + aoff + 8);
            cp16(sb + sldoff,                 Bh_ + boff);
            cp16(sb + sldoff + 16,            Bh_ + boff + 8);
            cp16(sb + GTILE*2 + sldoff,       Bl_ + boff);
            cp16(sb + GTILE*2 + sldoff + 16,  Bl_ + boff + 8);
            cp_commit();
            cp_wait1();
        } else {
            cp_wait0();
        }
        __syncthreads();

        const int st = kt & 1;
        const u32 saS = sbase  + st * GSTAGE * 2;
        const u32 sbS = sBbase + st * GSTAGE * 2;

#pragma unroll
        for (int s = 0; s < 2; s++) {
            u32 af[2][2][4];
#pragma unroll
            for (int hl = 0; hl < 2; hl++)
#pragma unroll
                for (int mf = 0; mf < 2; mf++)
                    ldsm4(af[hl][mf][0], af[hl][mf][1], af[hl][mf][2], af[hl][mf][3],
                          saS + (u32)(hl * GTILE * 2)
                              + (u32)((wm * 32 + mf * 16) * SASTR * 2)
                              + (u32)(s * 32) + a_lo);
#pragma unroll
            for (int np = 0; np < 4; np++) {
                u32 ba = sbS + (u32)((wn * 64 + np * 16) * SASTR * 2)
                             + (u32)(s * 32) + b_lo;
                u32 bh0[2], bh1[2], bl0[2], bl1[2];
                ldsm4(bh0[0], bh0[1], bh1[0], bh1[1], ba);
                ldsm4(bl0[0], bl0[1], bl1[0], bl1[1], ba + (u32)(GTILE * 2));
#pragma unroll
                for (int mf = 0; mf < 2; mf++) {
                    mma_bf16(acc[mf][2*np],   af[0][mf], bh0);
                    mma_bf16(acc[mf][2*np],   af[0][mf], bl0);
                    mma_bf16(acc[mf][2*np],   af[1][mf], bh0);
                    mma_bf16(acc[mf][2*np+1], af[0][mf], bh1);
                    mma_bf16(acc[mf][2*np+1], af[0][mf], bl1);
                    mma_bf16(acc[mf][2*np+1], af[1][mf], bh1);
                }
            }
        }
        __syncthreads();
    }

    // ---- epilogue ----
#pragma unroll
    for (int mf = 0; mf < 2; mf++) {
        int r0 = m0 + wm * 32 + mf * 16 + g;
#pragma unroll
        for (int nf = 0; nf < 8; nf++) {
            int c = n0 + wn * 64 + nf * 8 + 2 * tig;
            float b0 = bias[c], b1 = bias[c + 1];
            float v0 = acc[mf][nf][0] + b0, v1 = acc[mf][nf][1] + b1;
            float v2 = acc[mf][nf][2] + b0, v3 = acc[mf][nf][3] + b1;
            if (MODE == 0) {
                *(float2*)&Cf[(size_t)r0 * N + c]       = make_float2(v0, v1);
                *(float2*)&Cf[(size_t)(r0 + 8) * N + c] = make_float2(v2, v3);
            } else {
                v0 *= scale; v1 *= scale; v2 *= scale; v3 *= scale;
                float h0 = __bfloat162float(__float2bfloat16(v0));
                float h1 = __bfloat162float(__float2bfloat16(v1));
                float h2 = __bfloat162float(__float2bfloat16(v2));
                float h3 = __bfloat162float(__float2bfloat16(v3));
                *(u32*)&Ch_[(size_t)r0 * N + c]       = packbf(h0, h1);
                *(u32*)&Ch_[(size_t)(r0 + 8) * N + c] = packbf(h2, h3);
                *(u32*)&Cl_[(size_t)r0 * N + c]       = packbf(v0 - h0, v1 - h1);
                *(u32*)&Cl_[(size_t)(r0 + 8) * N + c] = packbf(v2 - h2, v3 - h3);
            }
        }
    }
}

// fused Q/K/V projection: grid.x = 18 (0-15: Q tiles, 16: K, 17: V)
__global__ __launch_bounds__(256, 2)
void gemm_qkv(const u16* __restrict__ xh, const u16* __restrict__ xl,
              const u16* __restrict__ wqh, const u16* __restrict__ wql,
              const u16* __restrict__ wkh, const u16* __restrict__ wkl,
              const u16* __restrict__ wvh, const u16* __restrict__ wvl,
              const float* __restrict__ bq, const float* __restrict__ bk,
              const float* __restrict__ bv,
              u16* Qh, u16* Ql, u16* Kh, u16* Kl, u16* Vh, u16* Vl)
{
    extern __shared__ u16 smem[];
    int bx = blockIdx.x, m0 = blockIdx.y * 128;
    if (bx < 16) {
        gemm_core<1>(xh, xl, wqh, wql, bq, nullptr, Qh, Ql,
                     DMOD, DMOD, QSCALE, m0, bx * 128, smem);
    } else if (bx == 16) {
        gemm_core<1>(xh, xl, wkh, wkl, bk, nullptr, Kh, Kl,
                     DH, DMOD, 1.f, m0, 0, smem);
    } else {
        gemm_core<1>(xh, xl, wvh, wvl, bv, nullptr, Vh, Vl,
                     DH, DMOD, 1.f, m0, 0, smem);
    }
}

__global__ __launch_bounds__(256, 2)
void gemm_o(const u16* __restrict__ aoh, const u16* __restrict__ aol,
            const u16* __restrict__ woh, const u16* __restrict__ wol,
            const float* __restrict__ bo, float* __restrict__ out)
{
    extern __shared__ u16 smem[];
    gemm_core<0>(aoh, aol, woh, wol, bo, out, nullptr, nullptr,
                 DMOD, DMOD, 1.f, blockIdx.y * 128, blockIdx.x * 128, smem);
}

// ============================================================================
// flash attention: 256 thr (8 warps -> 2 warps/SMSP for softmax/MMA overlap),
// 128 q-rows per block, 64-key tiles, cp.async double-buffered,
// ldmatrix (+trans for V), bf16x3 HMMA.
// ============================================================================
#define KSTR   136                      // 272 B row stride, 16B-aligned
#define FTILE  (64 * KSTR)              // 8704 shorts per tile
#define FSTAGE (4 * FTILE)              // Kh,Kl,Vh,Vl
#define FLASH_SMEM (2 * FSTAGE * 2)     // 139264 B

__global__ __launch_bounds__(256)
void flash_mma(const u16* __restrict__ Qh_, const u16* __restrict__ Ql_,
               const u16* __restrict__ Kh_, const u16* __restrict__ Kl_,
               const u16* __restrict__ Vh_, const u16* __restrict__ Vl_,
               u16* __restrict__ AOh_, u16* __restrict__ AOl_)
{
    extern __shared__ u16 smem[];
    const u32 sbase = (u32)__cvta_generic_to_shared(smem);

    const int tid = threadIdx.x;
    const int w = tid >> 5, lane = tid & 31;
    const int g = lane >> 2, tig = lane & 3;
    const int b = blockIdx.y >> 4, h = blockIdx.y & 15;
    const int qrow = blockIdx.x * 128 + w * 16 + g;

    const u32 kb_lo = (u32)(((((lane >> 4) << 3) + (lane & 7)) * KSTR
                             + (((lane >> 3) & 1) << 3)) * 2);
    const u32 vb_lo = (u32)((((((lane >> 3) & 1) << 3) + (lane & 7)) * KSTR
                             + ((lane >> 4) << 3)) * 2);

    // ---- prefetch stage 0 ----
    {
        const size_t base = (size_t)(b * SEQ) * DH;
#pragma unroll
        for (int i = tid; i < 1024; i += 256) {
            int r = i >> 4, c = (i & 15) * 8;
            size_t go = base + (size_t)r * DH + c;
            u32 d = sbase + (u32)((r * KSTR + c) * 2);
            cp16(d,                 Kh_ + go);
            cp16(d + FTILE*2,       Kl_ + go);
            cp16(d + 2*FTILE*2,     Vh_ + go);
            cp16(d + 3*FTILE*2,     Vl_ + go);
        }
        cp_commit();
    }

    // ---- Q fragments resident in registers (hi/lo) ----
    u32 qf[2][8][4];
    {
        size_t qb = (size_t)(b * SEQ + qrow) * DMOD + h * DH;
#pragma unroll
        for (int s = 0; s < 8; s++) {
            int col = s * 16 + 2 * tig;
            qf[0][s][0] = *(const u32*)(Qh_ + qb + col);
            qf[0][s][1] = *(const u32*)(Qh_ + qb + 8ull * DMOD + col);
            qf[0][s][2] = *(const u32*)(Qh_ + qb + col + 8);
            qf[0][s][3] = *(const u32*)(Qh_ + qb + 8ull * DMOD + col + 8);
            qf[1][s][0] = *(const u32*)(Ql_ + qb + col);
            qf[1][s][1] = *(const u32*)(Ql_ + qb + 8ull * DMOD + col);
            qf[1][s][2] = *(const u32*)(Ql_ + qb + col + 8);
            qf[1][s][3] = *(const u32*)(Ql_ + qb + 8ull * DMOD + col + 8);
        }
    }

    float pacc[16][4];
#pragma unroll
    for (int i = 0; i < 16; i++)
#pragma unroll
        for (int e = 0; e < 4; e++) pacc[i][e] = 0.f;
    float m0 = -1e30f, m1 = -1e30f, l0 = 0.f, l1 = 0.f;

    const int NT = SEQ / 64;
    for (int it = 0; it < NT; it++) {
        if (it + 1 < NT) {
            int st = (it + 1) & 1;
            const size_t base = (size_t)(b * SEQ + (it + 1) * 64) * DH;
            u32 sst = sbase + (u32)(st * FSTAGE * 2);
#pragma unroll
            for (int i = tid; i < 1024; i += 256) {
                int r = i >> 4, c = (i & 15) * 8;
                size_t go = base + (size_t)r * DH + c;
                u32 d = sst + (u32)((r * KSTR + c) * 2);
                cp16(d,             Kh_ + go);
                cp16(d + FTILE*2,   Kl_ + go);
                cp16(d + 2*FTILE*2, Vh_ + go);
                cp16(d + 3*FTILE*2, Vl_ + go);
            }
            cp_commit();
            cp_wait1();
        } else {
            cp_wait0();
        }
        __syncthreads();

        const u32 sst = sbase + (u32)((it & 1) * FSTAGE * 2);
        const u32 sKh = sst, sKl = sst + FTILE*2;
        const u32 sVh = sst + 2*FTILE*2, sVl = sst + 3*FTILE*2;

        // ---- scores S = Q K^T ----
        float sa[8][4];
#pragma unroll
        for (int nf = 0; nf < 8; nf++)
#pragma unroll
            for (int e = 0; e < 4; e++) sa[nf][e] = 0.f;

#pragma unroll
        for (int s = 0; s < 8; s++) {
#pragma unroll
            for (int np = 0; np < 4; np++) {
                u32 ba = (u32)(np * 16 * KSTR * 2) + (u32)(s * 32) + kb_lo;
                u32 bh0[2], bh1[2], bl0[2], bl1[2];
                ldsm4(bh0[0], bh0[1], bh1[0], bh1[1], sKh + ba);
                ldsm4(bl0[0], bl0[1], bl1[0], bl1[1], sKl + ba);
                mma_bf16(sa[2*np],   qf[0][s], bh0);
                mma_bf16(sa[2*np],   qf[0][s], bl0);
                mma_bf16(sa[2*np],   qf[1][s], bh0);
                mma_bf16(sa[2*np+1], qf[0][s], bh1);
                mma_bf16(sa[2*np+1], qf[0][s], bl1);
                mma_bf16(sa[2*np+1], qf[1][s], bh1);
            }
        }

        // ---- online softmax ----
        float mx0 = -1e30f, mx1 = -1e30f;
#pragma unroll
        for (int nf = 0; nf < 8; nf++) {
            mx0 = fmaxf(mx0, fmaxf(sa[nf][0], sa[nf][1]));
            mx1 = fmaxf(mx1, fmaxf(sa[nf][2], sa[nf][3]));
        }
        mx0 = fmaxf(mx0, __shfl_xor_sync(0xffffffffu, mx0, 1));
        mx0 = fmaxf(mx0, __shfl_xor_sync(0xffffffffu, mx0, 2));
        mx1 = fmaxf(mx1, __shfl_xor_sync(0xffffffffu, mx1, 1));
        mx1 = fmaxf(mx1, __shfl_xor_sync(0xffffffffu, mx1, 2));
        float nm0 = fmaxf(m0, mx0), nm1 = fmaxf(m1, mx1);
        float corr0 = __expf(m0 - nm0), corr1 = __expf(m1 - nm1);
        m0 = nm0; m1 = nm1;

        u32 aph[4][4], apl[4][4];
        float rs0 = 0.f, rs1 = 0.f;
#pragma unroll
        for (int nf = 0; nf < 8; nf++) {
            float p0 = __expf(sa[nf][0] - nm0);
            float p1 = __expf(sa[nf][1] - nm0);
            float p2 = __expf(sa[nf][2] - nm1);
            float p3 = __expf(sa[nf][3] - nm1);
            rs0 += p0 + p1; rs1 += p2 + p3;
            float h0 = __bfloat162float(__float2bfloat16(p0));
            float h1 = __bfloat162float(__float2bfloat16(p1));
            float h2 = __bfloat162float(__float2bfloat16(p2));
            float h3 = __bfloat162float(__float2bfloat16(p3));
            int ks = nf >> 1, pt = (nf & 1) * 2;
            aph[ks][pt]     = packbf(h0, h1);
            aph[ks][pt + 1] = packbf(h2, h3);
            apl[ks][pt]     = packbf(p0 - h0, p1 - h1);
            apl[ks][pt + 1] = packbf(p2 - h2, p3 - h3);
        }
        rs0 += __shfl_xor_sync(0xffffffffu, rs0, 1);
        rs0 += __shfl_xor_sync(0xffffffffu, rs0, 2);
        rs1 += __shfl_xor_sync(0xffffffffu, rs1, 1);
        rs1 += __shfl_xor_sync(0xffffffffu, rs1, 2);
        l0 = l0 * corr0 + rs0;
        l1 = l1 * corr1 + rs1;
#pragma unroll
        for (int nf = 0; nf < 16; nf++) {
            pacc[nf][0] *= corr0; pacc[nf][1] *= corr0;
            pacc[nf][2] *= corr1; pacc[nf][3] *= corr1;
        }

        // ---- pacc += P V (V row-major via ldmatrix.trans) ----
#pragma unroll
        for (int ks = 0; ks < 4; ks++) {
#pragma unroll
            for (int np = 0; np < 8; np++) {
                u32 va = (u32)((ks * 16 * KSTR + np * 16) * 2) + vb_lo;
                u32 bh0[2], bh1[2], bl0[2], bl1[2];
                ldsm4t(bh0[0], bh0[1], bh1[0], bh1[1], sVh + va);
                ldsm4t(bl0[0], bl0[1], bl1[0], bl1[1], sVl + va);
                mma_bf16(pacc[2*np],   aph[ks], bh0);
                mma_bf16(pacc[2*np],   aph[ks], bl0);
                mma_bf16(pacc[2*np],   apl[ks], bh0);
                mma_bf16(pacc[2*np+1], aph[ks], bh1);
                mma_bf16(pacc[2*np+1], aph[ks], bl1);
                mma_bf16(pacc[2*np+1], apl[ks], bh1);
            }
        }
        __syncthreads();
    }

    // ---- epilogue ----
    float inv0 = 1.f / l0, inv1 = 1.f / l1;
    size_t row0 = (size_t)(b * SEQ + qrow) * DMOD + h * DH;
#pragma unroll
    for (int nf = 0; nf < 16; nf++) {
        int c = nf * 8 + 2 * tig;
        float v0 = pacc[nf][0] * inv0, v1 = pacc[nf][1] * inv0;
        float v2 = pacc[nf][2] * inv1, v3 = pacc[nf][3] * inv1;
        float h0 = __bfloat162float(__float2bfloat16(v0));
        float h1 = __bfloat162float(__float2bfloat16(v1));
        float h2 = __bfloat162float(__float2bfloat16(v2));
        float h3 = __bfloat162float(__float2bfloat16(v3));
        *(u32*)(AOh_ + row0 + c)              = packbf(h0, h1);
        *(u32*)(AOh_ + row0 + 8ull*DMOD + c)  = packbf(h2, h3);
        *(u32*)(AOl_ + row0 + c)              = packbf(v0 - h0, v1 - h1);
        *(u32*)(AOl_ + row0 + 8ull*DMOD + c)  = packbf(v2 - h2, v3 - h3);
    }
}

// ---------------- launch ----------------
extern "C" void kernel_launch(void* const* d_in, const int* in_sizes, int n_in,
                              void* d_out, int out_size)
{
    (void)in_sizes; (void)n_in; (void)out_size;
    const float* x  = (const float*)d_in[0];
    const float* Wq = (const float*)d_in[1];
    const float* bq = (const float*)d_in[2];
    const float* Wk = (const float*)d_in[3];
    const float* bk = (const float*)d_in[4];
    const float* Wv = (const float*)d_in[5];
    const float* bv = (const float*)d_in[6];
    const float* Wo = (const float*)d_in[7];
    const float* bo = (const float*)d_in[8];
    float* out = (float*)d_out;

    void *xh,*xl,*wqh,*wql,*wkh,*wkl,*wvh,*wvl,*woh,*wol;
    void *qh,*ql,*kh,*kl,*vh,*vl,*aoh,*aol;
    cudaGetSymbolAddress(&xh,  g_xh);   cudaGetSymbolAddress(&xl,  g_xl);
    cudaGetSymbolAddress(&wqh, g_WqTh); cudaGetSymbolAddress(&wql, g_WqTl);
    cudaGetSymbolAddress(&wkh, g_WkTh); cudaGetSymbolAddress(&wkl, g_WkTl);
    cudaGetSymbolAddress(&wvh, g_WvTh); cudaGetSymbolAddress(&wvl, g_WvTl);
    cudaGetSymbolAddress(&woh, g_WoTh); cudaGetSymbolAddress(&wol, g_WoTl);
    cudaGetSymbolAddress(&qh,  g_Qh);   cudaGetSymbolAddress(&ql,  g_Ql);
    cudaGetSymbolAddress(&kh,  g_Kh);   cudaGetSymbolAddress(&kl,  g_Kl);
    cudaGetSymbolAddress(&vh,  g_Vh);   cudaGetSymbolAddress(&vl,  g_Vl);
    cudaGetSymbolAddress(&aoh, g_AOh);  cudaGetSymbolAddress(&aol, g_AOl);

    cudaFuncSetAttribute(gemm_qkv,
        cudaFuncAttributeMaxDynamicSharedMemorySize, GEMM_SMEM);
    cudaFuncSetAttribute(gemm_o,
        cudaFuncAttributeMaxDynamicSharedMemorySize, GEMM_SMEM);
    cudaFuncSetAttribute(flash_mma,
        cudaFuncAttributeMaxDynamicSharedMemorySize, FLASH_SMEM);

    // 0) split inputs
    int n4 = MTOK * DMOD / 4;
    split_f32<<<(n4 + 255) / 256, 256>>>(x, (u16*)xh, (u16*)xl, n4);
    wtsplit<<<dim3(DMOD/32, DMOD/32), dim3(32, 8)>>>(Wq, (u16*)wqh, (u16*)wql, DMOD, DMOD);
    wtsplit<<<dim3(DH/32,   DMOD/32), dim3(32, 8)>>>(Wk, (u16*)wkh, (u16*)wkl, DMOD, DH);
    wtsplit<<<dim3(DH/32,   DMOD/32), dim3(32, 8)>>>(Wv, (u16*)wvh, (u16*)wvl, DMOD, DH);
    wtsplit<<<dim3(DMOD/32, DMOD/32), dim3(32, 8)>>>(Wo, (u16*)woh, (u16*)wol, DMOD, DMOD);

    // 1) fused Q/K/V projections
    gemm_qkv<<<dim3(18, MTOK/128), 256, GEMM_SMEM>>>(
        (u16*)xh, (u16*)xl, (u16*)wqh, (u16*)wql, (u16*)wkh, (u16*)wkl,
        (u16*)wvh, (u16*)wvl, bq, bk, bv,
        (u16*)qh, (u16*)ql, (u16*)kh, (u16*)kl, (u16*)vh, (u16*)vl);

    // 2) flash attention (128 q-rows/block, 8 warps)
    flash_mma<<<dim3(SEQ/128, NB*NH), 256, FLASH_SMEM>>>(
        (u16*)qh, (u16*)ql, (u16*)kh, (u16*)kl, (u16*)vh, (u16*)vl,
        (u16*)aoh, (u16*)aol);

    // 3) out = AO @ Wo + bo (fp32)
    gemm_o<<<dim3(DMOD/128, MTOK/128), 256, GEMM_SMEM>>>(
        (u16*)aoh, (u16*)aol, (u16*)woh, (u16*)wol, bo, out);
}

// round 13
// speedup vs baseline: 1.9249x; 1.4334x over previous
#include <cuda_runtime.h>
#include <cuda_fp16.h>

// ---------------- problem constants ----------------
#define MTOK  4096
#define DMOD  2048
#define NH    16
#define DH    128
#define SEQ   2048
#define NB    2

typedef unsigned int u32;
typedef unsigned short u16;

// ---------------- scratch (device globals; 16B-aligned for cp.async) ------
__device__ __align__(256) u16 g_xh [MTOK*DMOD], g_xl [MTOK*DMOD];
__device__ __align__(256) u16 g_WqTh[DMOD*DMOD];
__device__ __align__(256) u16 g_WkTh[DH*DMOD];
__device__ __align__(256) u16 g_WvTh[DH*DMOD];
__device__ __align__(256) u16 g_WoTh[DMOD*DMOD];
__device__ __align__(256) u16 g_Qh [MTOK*DMOD], g_Ql [MTOK*DMOD];
__device__ __align__(256) u16 g_Kh [MTOK*DH];
__device__ __align__(256) u16 g_Vh [MTOK*DH],   g_Vl [MTOK*DH];
__device__ __align__(256) u16 g_AOh[MTOK*DMOD], g_AOl[MTOK*DMOD];

// ---------------- PTX helpers ----------------
__device__ __forceinline__ void mma_f16(float* c, const u32* a, const u32* b) {
    asm("mma.sync.aligned.m16n8k16.row.col.f32.f16.f16.f32 "
        "{%0,%1,%2,%3},{%4,%5,%6,%7},{%8,%9},{%0,%1,%2,%3};"
        : "+f"(c[0]), "+f"(c[1]), "+f"(c[2]), "+f"(c[3])
        : "r"(a[0]), "r"(a[1]), "r"(a[2]), "r"(a[3]), "r"(b[0]), "r"(b[1]));
}
__device__ __forceinline__ void ldsm4(u32& r0, u32& r1, u32& r2, u32& r3, u32 a) {
    asm volatile("ldmatrix.sync.aligned.m8n8.x4.shared.b16 {%0,%1,%2,%3},[%4];"
                 : "=r"(r0), "=r"(r1), "=r"(r2), "=r"(r3) : "r"(a));
}
__device__ __forceinline__ void ldsm4t(u32& r0, u32& r1, u32& r2, u32& r3, u32 a) {
    asm volatile("ldmatrix.sync.aligned.m8n8.x4.trans.shared.b16 {%0,%1,%2,%3},[%4];"
                 : "=r"(r0), "=r"(r1), "=r"(r2), "=r"(r3) : "r"(a));
}
__device__ __forceinline__ void cp16(u32 dst, const void* src) {
    asm volatile("cp.async.cg.shared.global [%0], [%1], 16;" :: "r"(dst), "l"(src));
}
__device__ __forceinline__ void cp_commit() { asm volatile("cp.async.commit_group;"); }
__device__ __forceinline__ void cp_wait0()  { asm volatile("cp.async.wait_group 0;"); }
__device__ __forceinline__ void cp_wait1()  { asm volatile("cp.async.wait_group 1;"); }

__device__ __forceinline__ u32 packh(float a, float b) {   // a -> low 16 bits
    __half2 t = __floats2half2_rn(a, b);
    return *reinterpret_cast<u32*>(&t);
}
__device__ __forceinline__ float ex2(float x) {
    float y; asm("ex2.approx.ftz.f32 %0, %1;" : "=f"(y) : "f"(x)); return y;
}

// ---------------- converters ----------------
// x fp32 -> hi/lo fp16
__global__ void split_f32(const float* __restrict__ in,
                          u16* __restrict__ h, u16* __restrict__ l, int n4) {
    int i = blockIdx.x * blockDim.x + threadIdx.x;
    if (i >= n4) return;
    float4 v = ((const float4*)in)[i];
    u32 h0 = packh(v.x, v.y);
    u32 h1 = packh(v.z, v.w);
    __half2 a = *(__half2*)&h0, b = *(__half2*)&h1;
    ((u32*)h)[2*i]   = h0;
    ((u32*)h)[2*i+1] = h1;
    ((u32*)l)[2*i]   = packh(v.x - __low2float(a), v.y - __high2float(a));
    ((u32*)l)[2*i+1] = packh(v.z - __low2float(b), v.w - __high2float(b));
}

// W[K][N] fp32 -> WT[N][K] fp16 (hi only)
__global__ void wtsplit(const float* __restrict__ W,
                        u16* __restrict__ Th, int K, int N) {
    __shared__ float t[32][33];
    int nt = blockIdx.x * 32, kt = blockIdx.y * 32;
    int tx = threadIdx.x, ty = threadIdx.y;
#pragma unroll
    for (int j = 0; j < 4; j++)
        t[ty + 8*j][tx] = W[(size_t)(kt + ty + 8*j) * N + nt + tx];
    __syncthreads();
#pragma unroll
    for (int j = 0; j < 4; j++) {
        float v = t[tx][ty + 8*j];
        size_t idx = (size_t)(nt + ty + 8*j) * K + kt + tx;
        ((__half*)Th)[idx] = __float2half_rn(v);
    }
}

// ============================================================================
// fp16 2-term GEMM: C = (Ah+Al)@Bh^T + bias. 128x128 tile, BK=32, 256 thr,
// cp.async double-buffered, ldmatrix. 2 CTAs/SM.
// MODE 0: fp32 out.  MODE 1: hi/lo fp16 out.  MODE 2: hi fp16 only.
// ============================================================================
#define SASTR 40                     // padded smem row stride (shorts) = 80 B
#define GTILE (128 * SASTR)          // 5120 shorts per tile
#define GEMM_SMEM (6 * GTILE * 2)    // A: 2 stages x (h+l), B: 2 stages x h = 61440 B

template<int MODE>
__device__ __forceinline__ void gemm_core(
    const u16* __restrict__ Ah_, const u16* __restrict__ Al_,
    const u16* __restrict__ Bh_,
    const float* __restrict__ bias,
    float* __restrict__ Cf, u16* __restrict__ Ch_, u16* __restrict__ Cl_,
    int N, int K, int m0, int n0, u16* smem)
{
    const int tid  = threadIdx.x;
    const int warp = tid >> 5, lane = tid & 31;
    const int g = lane >> 2, tig = lane & 3;
    const int wm = warp >> 1, wn = warp & 1;

    const u32 sbase  = (u32)__cvta_generic_to_shared(smem);
    const u32 sBbase = sbase + 4 * GTILE * 2;

    float acc[2][8][4];
#pragma unroll
    for (int i = 0; i < 2; i++)
#pragma unroll
        for (int j = 0; j < 8; j++)
#pragma unroll
            for (int e = 0; e < 4; e++) acc[i][j][e] = 0.f;

    const int lr = tid >> 1, lc = (tid & 1) * 16;
    const u32 sldoff = (u32)(lr * SASTR + lc) * 2;

    const u32 a_lo = (u32)(((lane & 15) * SASTR + ((lane >> 4) << 3)) * 2);
    const u32 b_lo = (u32)(((((lane >> 4) << 3) + (lane & 7)) * SASTR
                            + (((lane >> 3) & 1) << 3)) * 2);

    const int nk = K / 32;
    auto prefetch = [&](int st, int kt) {
        u32 aB = sbase  + st * (2 * GTILE * 2);
        u32 bB = sBbase + st * (GTILE * 2);
        size_t aoff = (size_t)(m0 + lr) * K + kt + lc;
        size_t boff = (size_t)(n0 + lr) * K + kt + lc;
        cp16(aB + sldoff,                 Ah_ + aoff);
        cp16(aB + sldoff + 16,            Ah_ + aoff + 8);
        cp16(aB + GTILE*2 + sldoff,       Al_ + aoff);
        cp16(aB + GTILE*2 + sldoff + 16,  Al_ + aoff + 8);
        cp16(bB + sldoff,                 Bh_ + boff);
        cp16(bB + sldoff + 16,            Bh_ + boff + 8);
        cp_commit();
    };
    prefetch(0, 0);

    for (int kt = 0; kt < nk; kt++) {
        if (kt + 1 < nk) {
            prefetch((kt + 1) & 1, (kt + 1) * 32);
            cp_wait1();
        } else {
            cp_wait0();
        }
        __syncthreads();

        const int st = kt & 1;
        const u32 saS = sbase  + st * (2 * GTILE * 2);
        const u32 sbS = sBbase + st * (GTILE * 2);

#pragma unroll
        for (int s = 0; s < 2; s++) {
            u32 af[2][2][4];
#pragma unroll
            for (int hl = 0; hl < 2; hl++)
#pragma unroll
                for (int mf = 0; mf < 2; mf++)
                    ldsm4(af[hl][mf][0], af[hl][mf][1], af[hl][mf][2], af[hl][mf][3],
                          saS + (u32)(hl * GTILE * 2)
                              + (u32)((wm * 32 + mf * 16) * SASTR * 2)
                              + (u32)(s * 32) + a_lo);
#pragma unroll
            for (int np = 0; np < 4; np++) {
                u32 ba = sbS + (u32)((wn * 64 + np * 16) * SASTR * 2)
                             + (u32)(s * 32) + b_lo;
                u32 bh0[2], bh1[2];
                ldsm4(bh0[0], bh0[1], bh1[0], bh1[1], ba);
#pragma unroll
                for (int mf = 0; mf < 2; mf++) {
                    mma_f16(acc[mf][2*np],   af[0][mf], bh0);
                    mma_f16(acc[mf][2*np],   af[1][mf], bh0);
                    mma_f16(acc[mf][2*np+1], af[0][mf], bh1);
                    mma_f16(acc[mf][2*np+1], af[1][mf], bh1);
                }
            }
        }
        __syncthreads();
    }

    // ---- epilogue ----
#pragma unroll
    for (int mf = 0; mf < 2; mf++) {
        int r0 = m0 + wm * 32 + mf * 16 + g;
#pragma unroll
        for (int nf = 0; nf < 8; nf++) {
            int c = n0 + wn * 64 + nf * 8 + 2 * tig;
            float b0 = bias[c], b1 = bias[c + 1];
            float v0 = acc[mf][nf][0] + b0, v1 = acc[mf][nf][1] + b1;
            float v2 = acc[mf][nf][2] + b0, v3 = acc[mf][nf][3] + b1;
            if (MODE == 0) {
                *(float2*)&Cf[(size_t)r0 * N + c]       = make_float2(v0, v1);
                *(float2*)&Cf[(size_t)(r0 + 8) * N + c] = make_float2(v2, v3);
            } else if (MODE == 2) {
                *(u32*)&Ch_[(size_t)r0 * N + c]       = packh(v0, v1);
                *(u32*)&Ch_[(size_t)(r0 + 8) * N + c] = packh(v2, v3);
            } else {
                u32 hp0 = packh(v0, v1), hp1 = packh(v2, v3);
                __half2 a = *(__half2*)&hp0, bb = *(__half2*)&hp1;
                *(u32*)&Ch_[(size_t)r0 * N + c]       = hp0;
                *(u32*)&Ch_[(size_t)(r0 + 8) * N + c] = hp1;
                *(u32*)&Cl_[(size_t)r0 * N + c] =
                    packh(v0 - __low2float(a), v1 - __high2float(a));
                *(u32*)&Cl_[(size_t)(r0 + 8) * N + c] =
                    packh(v2 - __low2float(bb), v3 - __high2float(bb));
            }
        }
    }
}

// fused Q/K/V projection: grid.x = 18 (0-15: Q tiles, 16: K, 17: V)
__global__ __launch_bounds__(256, 2)
void gemm_qkv(const u16* __restrict__ xh, const u16* __restrict__ xl,
              const u16* __restrict__ wqh, const u16* __restrict__ wkh,
              const u16* __restrict__ wvh,
              const float* __restrict__ bq, const float* __restrict__ bk,
              const float* __restrict__ bv,
              u16* Qh, u16* Ql, u16* Kh, u16* Vh, u16* Vl)
{
    extern __shared__ u16 smem[];
    int bx = blockIdx.x, m0 = blockIdx.y * 128;
    if (bx < 16) {
        gemm_core<1>(xh, xl, wqh, bq, nullptr, Qh, Ql,
                     DMOD, DMOD, m0, bx * 128, smem);
    } else if (bx == 16) {
        gemm_core<2>(xh, xl, wkh, bk, nullptr, Kh, nullptr,
                     DH, DMOD, m0, 0, smem);
    } else {
        gemm_core<1>(xh, xl, wvh, bv, nullptr, Vh, Vl,
                     DH, DMOD, m0, 0, smem);
    }
}

__global__ __launch_bounds__(256, 2)
void gemm_o(const u16* __restrict__ aoh, const u16* __restrict__ aol,
            const u16* __restrict__ woh,
            const float* __restrict__ bo, float* __restrict__ out)
{
    extern __shared__ u16 smem[];
    gemm_core<0>(aoh, aol, woh, bo, out, nullptr, nullptr,
                 DMOD, DMOD, blockIdx.y * 128, blockIdx.x * 128, smem);
}

// ============================================================================
// flash attention: 256 thr (8 warps), 128 q-rows/block, 64-key tiles,
// cp.async double-buffered {Kh, Vh, Vl}, fp16 2-term MMA,
// softmax with 1/sqrt(DH) folded into the exp2 constant (Q stays unscaled).
// ============================================================================
#define KSTR   136                      // 272 B row stride, 16B-aligned
#define FTILE  (64 * KSTR)              // 8704 shorts per tile
#define FSTAGE (3 * FTILE)              // Kh, Vh, Vl
#define FLASH_SMEM (2 * FSTAGE * 2)     // 104448 B

__global__ __launch_bounds__(256)
void flash_mma(const u16* __restrict__ Qh_, const u16* __restrict__ Ql_,
               const u16* __restrict__ Kh_,
               const u16* __restrict__ Vh_, const u16* __restrict__ Vl_,
               u16* __restrict__ AOh_, u16* __restrict__ AOl_)
{
    extern __shared__ u16 smem[];
    const u32 sbase = (u32)__cvta_generic_to_shared(smem);
    const float SC = 1.4426950408889634f * 0.08838834764831845f;  // log2e/sqrt(128)

    const int tid = threadIdx.x;
    const int w = tid >> 5, lane = tid & 31;
    const int g = lane >> 2, tig = lane & 3;
    const int b = blockIdx.y >> 4, h = blockIdx.y & 15;
    const int qrow = blockIdx.x * 128 + w * 16 + g;

    const u32 kb_lo = (u32)(((((lane >> 4) << 3) + (lane & 7)) * KSTR
                             + (((lane >> 3) & 1) << 3)) * 2);
    const u32 vb_lo = (u32)((((((lane >> 3) & 1) << 3) + (lane & 7)) * KSTR
                             + ((lane >> 4) << 3)) * 2);

    // ---- prefetch stage 0 ----
    {
        const size_t base = (size_t)(b * SEQ) * DH;
#pragma unroll
        for (int i = tid; i < 1024; i += 256) {
            int r = i >> 4, c = (i & 15) * 8;
            size_t go = base + (size_t)r * DH + c;
            u32 d = sbase + (u32)((r * KSTR + c) * 2);
            cp16(d,             Kh_ + go);
            cp16(d + FTILE*2,   Vh_ + go);
            cp16(d + 2*FTILE*2, Vl_ + go);
        }
        cp_commit();
    }

    // ---- Q fragments resident in registers (hi/lo fp16) ----
    u32 qf[2][8][4];
    {
        size_t qb = (size_t)(b * SEQ + qrow) * DMOD + h * DH;
#pragma unroll
        for (int s = 0; s < 8; s++) {
            int col = s * 16 + 2 * tig;
            qf[0][s][0] = *(const u32*)(Qh_ + qb + col);
            qf[0][s][1] = *(const u32*)(Qh_ + qb + 8ull * DMOD + col);
            qf[0][s][2] = *(const u32*)(Qh_ + qb + col + 8);
            qf[0][s][3] = *(const u32*)(Qh_ + qb + 8ull * DMOD + col + 8);
            qf[1][s][0] = *(const u32*)(Ql_ + qb + col);
            qf[1][s][1] = *(const u32*)(Ql_ + qb + 8ull * DMOD + col);
            qf[1][s][2] = *(const u32*)(Ql_ + qb + col + 8);
            qf[1][s][3] = *(const u32*)(Ql_ + qb + 8ull * DMOD + col + 8);
        }
    }

    float pacc[16][4];
#pragma unroll
    for (int i = 0; i < 16; i++)
#pragma unroll
        for (int e = 0; e < 4; e++) pacc[i][e] = 0.f;
    float m0 = -1e30f, m1 = -1e30f, l0 = 0.f, l1 = 0.f;

    const int NT = SEQ / 64;
    for (int it = 0; it < NT; it++) {
        if (it + 1 < NT) {
            int st = (it + 1) & 1;
            const size_t base = (size_t)(b * SEQ + (it + 1) * 64) * DH;
            u32 sst = sbase + (u32)(st * FSTAGE * 2);
#pragma unroll
            for (int i = tid; i < 1024; i += 256) {
                int r = i >> 4, c = (i & 15) * 8;
                size_t go = base + (size_t)r * DH + c;
                u32 d = sst + (u32)((r * KSTR + c) * 2);
                cp16(d,             Kh_ + go);
                cp16(d + FTILE*2,   Vh_ + go);
                cp16(d + 2*FTILE*2, Vl_ + go);
            }
            cp_commit();
            cp_wait1();
        } else {
            cp_wait0();
        }
        __syncthreads();

        const u32 sst = sbase + (u32)((it & 1) * FSTAGE * 2);
        const u32 sKh = sst;
        const u32 sVh = sst + FTILE*2, sVl = sst + 2*FTILE*2;

        // ---- raw scores S = Q K^T (unscaled) ----
        float sa[8][4];
#pragma unroll
        for (int nf = 0; nf < 8; nf++)
#pragma unroll
            for (int e = 0; e < 4; e++) sa[nf][e] = 0.f;

#pragma unroll
        for (int s = 0; s < 8; s++) {
#pragma unroll
            for (int np = 0; np < 4; np++) {
                u32 ba = (u32)(np * 16 * KSTR * 2) + (u32)(s * 32) + kb_lo;
                u32 bh0[2], bh1[2];
                ldsm4(bh0[0], bh0[1], bh1[0], bh1[1], sKh + ba);
                mma_f16(sa[2*np],   qf[0][s], bh0);
                mma_f16(sa[2*np],   qf[1][s], bh0);
                mma_f16(sa[2*np+1], qf[0][s], bh1);
                mma_f16(sa[2*np+1], qf[1][s], bh1);
            }
        }

        // ---- online softmax (scale folded into SC) ----
        float mx0 = -1e30f, mx1 = -1e30f;
#pragma unroll
        for (int nf = 0; nf < 8; nf++) {
            mx0 = fmaxf(mx0, fmaxf(sa[nf][0], sa[nf][1]));
            mx1 = fmaxf(mx1, fmaxf(sa[nf][2], sa[nf][3]));
        }
        mx0 = fmaxf(mx0, __shfl_xor_sync(0xffffffffu, mx0, 1));
        mx0 = fmaxf(mx0, __shfl_xor_sync(0xffffffffu, mx0, 2));
        mx1 = fmaxf(mx1, __shfl_xor_sync(0xffffffffu, mx1, 1));
        mx1 = fmaxf(mx1, __shfl_xor_sync(0xffffffffu, mx1, 2));
        float nm0 = fmaxf(m0, mx0), nm1 = fmaxf(m1, mx1);
        float corr0 = ex2((m0 - nm0) * SC), corr1 = ex2((m1 - nm1) * SC);
        m0 = nm0; m1 = nm1;
        float nm0s = nm0 * SC, nm1s = nm1 * SC;

        u32 aph[4][4];                 // P fragments (fp16, single precision level)
        float rs0 = 0.f, rs1 = 0.f;
#pragma unroll
        for (int nf = 0; nf < 8; nf++) {
            float p0 = ex2(fmaf(sa[nf][0], SC, -nm0s));
            float p1 = ex2(fmaf(sa[nf][1], SC, -nm0s));
            float p2 = ex2(fmaf(sa[nf][2], SC, -nm1s));
            float p3 = ex2(fmaf(sa[nf][3], SC, -nm1s));
            rs0 += p0 + p1; rs1 += p2 + p3;
            int ks = nf >> 1, pt = (nf & 1) * 2;
            aph[ks][pt]     = packh(p0, p1);
            aph[ks][pt + 1] = packh(p2, p3);
        }
        rs0 += __shfl_xor_sync(0xffffffffu, rs0, 1);
        rs0 += __shfl_xor_sync(0xffffffffu, rs0, 2);
        rs1 += __shfl_xor_sync(0xffffffffu, rs1, 1);
        rs1 += __shfl_xor_sync(0xffffffffu, rs1, 2);
        l0 = l0 * corr0 + rs0;
        l1 = l1 * corr1 + rs1;
#pragma unroll
        for (int nf = 0; nf < 16; nf++) {
            pacc[nf][0] *= corr0; pacc[nf][1] *= corr0;
            pacc[nf][2] *= corr1; pacc[nf][3] *= corr1;
        }

        // ---- pacc += P (Vh + Vl)  (V row-major via ldmatrix.trans) ----
#pragma unroll
        for (int ks = 0; ks < 4; ks++) {
#pragma unroll
            for (int np = 0; np < 8; np++) {
                u32 va = (u32)((ks * 16 * KSTR + np * 16) * 2) + vb_lo;
                u32 bh0[2], bh1[2], bl0[2], bl1[2];
                ldsm4t(bh0[0], bh0[1], bh1[0], bh1[1], sVh + va);
                ldsm4t(bl0[0], bl0[1], bl1[0], bl1[1], sVl + va);
                mma_f16(pacc[2*np],   aph[ks], bh0);
                mma_f16(pacc[2*np],   aph[ks], bl0);
                mma_f16(pacc[2*np+1], aph[ks], bh1);
                mma_f16(pacc[2*np+1], aph[ks], bl1);
            }
        }
        __syncthreads();
    }

    // ---- epilogue: normalize, split hi/lo fp16, write AO ----
    float inv0 = 1.f / l0, inv1 = 1.f / l1;
    size_t row0 = (size_t)(b * SEQ + qrow) * DMOD + h * DH;
#pragma unroll
    for (int nf = 0; nf < 16; nf++) {
        int c = nf * 8 + 2 * tig;
        float v0 = pacc[nf][0] * inv0, v1 = pacc[nf][1] * inv0;
        float v2 = pacc[nf][2] * inv1, v3 = pacc[nf][3] * inv1;
        u32 hp0 = packh(v0, v1), hp1 = packh(v2, v3);
        __half2 a = *(__half2*)&hp0, bb = *(__half2*)&hp1;
        *(u32*)(AOh_ + row0 + c)             = hp0;
        *(u32*)(AOh_ + row0 + 8ull*DMOD + c) = hp1;
        *(u32*)(AOl_ + row0 + c) =
            packh(v0 - __low2float(a), v1 - __high2float(a));
        *(u32*)(AOl_ + row0 + 8ull*DMOD + c) =
            packh(v2 - __low2float(bb), v3 - __high2float(bb));
    }
}

// ---------------- launch ----------------
extern "C" void kernel_launch(void* const* d_in, const int* in_sizes, int n_in,
                              void* d_out, int out_size)
{
    (void)in_sizes; (void)n_in; (void)out_size;
    const float* x  = (const float*)d_in[0];
    const float* Wq = (const float*)d_in[1];
    const float* bq = (const float*)d_in[2];
    const float* Wk = (const float*)d_in[3];
    const float* bk = (const float*)d_in[4];
    const float* Wv = (const float*)d_in[5];
    const float* bv = (const float*)d_in[6];
    const float* Wo = (const float*)d_in[7];
    const float* bo = (const float*)d_in[8];
    float* out = (float*)d_out;

    void *xh,*xl,*wqh,*wkh,*wvh,*woh;
    void *qh,*ql,*kh,*vh,*vl,*aoh,*aol;
    cudaGetSymbolAddress(&xh,  g_xh);   cudaGetSymbolAddress(&xl,  g_xl);
    cudaGetSymbolAddress(&wqh, g_WqTh);
    cudaGetSymbolAddress(&wkh, g_WkTh);
    cudaGetSymbolAddress(&wvh, g_WvTh);
    cudaGetSymbolAddress(&woh, g_WoTh);
    cudaGetSymbolAddress(&qh,  g_Qh);   cudaGetSymbolAddress(&ql,  g_Ql);
    cudaGetSymbolAddress(&kh,  g_Kh);
    cudaGetSymbolAddress(&vh,  g_Vh);   cudaGetSymbolAddress(&vl,  g_Vl);
    cudaGetSymbolAddress(&aoh, g_AOh);  cudaGetSymbolAddress(&aol, g_AOl);

    cudaFuncSetAttribute(gemm_qkv,
        cudaFuncAttributeMaxDynamicSharedMemorySize, GEMM_SMEM);
    cudaFuncSetAttribute(gemm_o,
        cudaFuncAttributeMaxDynamicSharedMemorySize, GEMM_SMEM);
    cudaFuncSetAttribute(flash_mma,
        cudaFuncAttributeMaxDynamicSharedMemorySize, FLASH_SMEM);

    // 0) split inputs (weights: hi only)
    int n4 = MTOK * DMOD / 4;
    split_f32<<<(n4 + 255) / 256, 256>>>(x, (u16*)xh, (u16*)xl, n4);
    wtsplit<<<dim3(DMOD/32, DMOD/32), dim3(32, 8)>>>(Wq, (u16*)wqh, DMOD, DMOD);
    wtsplit<<<dim3(DH/32,   DMOD/32), dim3(32, 8)>>>(Wk, (u16*)wkh, DMOD, DH);
    wtsplit<<<dim3(DH/32,   DMOD/32), dim3(32, 8)>>>(Wv, (u16*)wvh, DMOD, DH);
    wtsplit<<<dim3(DMOD/32, DMOD/32), dim3(32, 8)>>>(Wo, (u16*)woh, DMOD, DMOD);

    // 1) fused Q/K/V projections (Q unscaled; scale folded into softmax)
    gemm_qkv<<<dim3(18, MTOK/128), 256, GEMM_SMEM>>>(
        (u16*)xh, (u16*)xl, (u16*)wqh, (u16*)wkh, (u16*)wvh, bq, bk, bv,
        (u16*)qh, (u16*)ql, (u16*)kh, (u16*)vh, (u16*)vl);

    // 2) flash attention
    flash_mma<<<dim3(SEQ/128, NB*NH), 256, FLASH_SMEM>>>(
        (u16*)qh, (u16*)ql, (u16*)kh, (u16*)vh, (u16*)vl,
        (u16*)aoh, (u16*)aol);

    // 3) out = AO @ Wo + bo (fp32)
    gemm_o<<<dim3(DMOD/128, MTOK/128), 256, GEMM_SMEM>>>(
        (u16*)aoh, (u16*)aol, (u16*)woh, bo, out);
}

// round 14
// speedup vs baseline: 2.2414x; 1.1645x over previous
#include <cuda_runtime.h>
#include <cuda_fp16.h>

// ---------------- problem constants ----------------
#define MTOK  4096
#define DMOD  2048
#define NH    16
#define DH    128
#define SEQ   2048
#define NB    2

typedef unsigned int u32;
typedef unsigned short u16;

// ---------------- scratch (device globals; 16B-aligned for cp.async) ------
__device__ __align__(256) u16 g_xh [MTOK*DMOD], g_xl [MTOK*DMOD];
__device__ __align__(256) u16 g_WqTh[DMOD*DMOD];
__device__ __align__(256) u16 g_WkTh[DH*DMOD];
__device__ __align__(256) u16 g_WvTh[DH*DMOD];
__device__ __align__(256) u16 g_WoTh[DMOD*DMOD];
__device__ __align__(256) u16 g_Qh [MTOK*DMOD];
__device__ __align__(256) u16 g_Kh [MTOK*DH];
__device__ __align__(256) u16 g_Vh [MTOK*DH];
__device__ __align__(256) u16 g_AOh[MTOK*DMOD], g_AOl[MTOK*DMOD];

// ---------------- PTX helpers ----------------
__device__ __forceinline__ void mma_f16(float* c, const u32* a, const u32* b) {
    asm("mma.sync.aligned.m16n8k16.row.col.f32.f16.f16.f32 "
        "{%0,%1,%2,%3},{%4,%5,%6,%7},{%8,%9},{%0,%1,%2,%3};"
        : "+f"(c[0]), "+f"(c[1]), "+f"(c[2]), "+f"(c[3])
        : "r"(a[0]), "r"(a[1]), "r"(a[2]), "r"(a[3]), "r"(b[0]), "r"(b[1]));
}
__device__ __forceinline__ void ldsm4(u32& r0, u32& r1, u32& r2, u32& r3, u32 a) {
    asm volatile("ldmatrix.sync.aligned.m8n8.x4.shared.b16 {%0,%1,%2,%3},[%4];"
                 : "=r"(r0), "=r"(r1), "=r"(r2), "=r"(r3) : "r"(a));
}
__device__ __forceinline__ void ldsm4t(u32& r0, u32& r1, u32& r2, u32& r3, u32 a) {
    asm volatile("ldmatrix.sync.aligned.m8n8.x4.trans.shared.b16 {%0,%1,%2,%3},[%4];"
                 : "=r"(r0), "=r"(r1), "=r"(r2), "=r"(r3) : "r"(a));
}
__device__ __forceinline__ void cp16(u32 dst, const void* src) {
    asm volatile("cp.async.cg.shared.global [%0], [%1], 16;" :: "r"(dst), "l"(src));
}
__device__ __forceinline__ void cp_commit() { asm volatile("cp.async.commit_group;"); }
__device__ __forceinline__ void cp_wait0()  { asm volatile("cp.async.wait_group 0;"); }
__device__ __forceinline__ void cp_wait1()  { asm volatile("cp.async.wait_group 1;"); }
__device__ __forceinline__ void cp_wait2()  { asm volatile("cp.async.wait_group 2;"); }

__device__ __forceinline__ u32 packh(float a, float b) {   // a -> low 16 bits
    __half2 t = __floats2half2_rn(a, b);
    return *reinterpret_cast<u32*>(&t);
}
__device__ __forceinline__ float ex2(float x) {
    float y; asm("ex2.approx.ftz.f32 %0, %1;" : "=f"(y) : "f"(x)); return y;
}

// ---------------- converters ----------------
// x fp32 -> hi/lo fp16
__global__ void split_f32(const float* __restrict__ in,
                          u16* __restrict__ h, u16* __restrict__ l, int n4) {
    int i = blockIdx.x * blockDim.x + threadIdx.x;
    if (i >= n4) return;
    float4 v = ((const float4*)in)[i];
    u32 h0 = packh(v.x, v.y);
    u32 h1 = packh(v.z, v.w);
    __half2 a = *(__half2*)&h0, b = *(__half2*)&h1;
    ((u32*)h)[2*i]   = h0;
    ((u32*)h)[2*i+1] = h1;
    ((u32*)l)[2*i]   = packh(v.x - __low2float(a), v.y - __high2float(a));
    ((u32*)l)[2*i+1] = packh(v.z - __low2float(b), v.w - __high2float(b));
}

// W[K][N] fp32 -> WT[N][K] fp16 (hi only)
__global__ void wtsplit(const float* __restrict__ W,
                        u16* __restrict__ Th, int K, int N) {
    __shared__ float t[32][33];
    int nt = blockIdx.x * 32, kt = blockIdx.y * 32;
    int tx = threadIdx.x, ty = threadIdx.y;
#pragma unroll
    for (int j = 0; j < 4; j++)
        t[ty + 8*j][tx] = W[(size_t)(kt + ty + 8*j) * N + nt + tx];
    __syncthreads();
#pragma unroll
    for (int j = 0; j < 4; j++) {
        float v = t[tx][ty + 8*j];
        size_t idx = (size_t)(nt + ty + 8*j) * K + kt + tx;
        ((__half*)Th)[idx] = __float2half_rn(v);
    }
}

// ============================================================================
// fp16 2-term GEMM: C = (Ah+Al)@Bh^T + bias. 128x128 tile, BK=32, 256 thr,
// cp.async 3-stage pipeline, ldmatrix. 2 CTAs/SM.
// MODE 0: fp32 out.  MODE 2: fp16 hi out.
// ============================================================================
#define SASTR 40                     // padded smem row stride (shorts) = 80 B
#define GTILE (128 * SASTR)          // 5120 shorts per tile
#define GSTG  (3 * GTILE * 2)        // stage bytes: Ah + Al + Bh = 30720
#define GEMM_SMEM (3 * GSTG)         // 3 stages = 92160 B

template<int MODE>
__device__ __forceinline__ void gemm_core(
    const u16* __restrict__ Ah_, const u16* __restrict__ Al_,
    const u16* __restrict__ Bh_,
    const float* __restrict__ bias,
    float* __restrict__ Cf, u16* __restrict__ Ch_,
    int N, int K, int m0, int n0, u16* smem)
{
    const int tid  = threadIdx.x;
    const int warp = tid >> 5, lane = tid & 31;
    const int g = lane >> 2, tig = lane & 3;
    const int wm = warp >> 1, wn = warp & 1;

    const u32 sbase = (u32)__cvta_generic_to_shared(smem);

    float acc[2][8][4];
#pragma unroll
    for (int i = 0; i < 2; i++)
#pragma unroll
        for (int j = 0; j < 8; j++)
#pragma unroll
            for (int e = 0; e < 4; e++) acc[i][j][e] = 0.f;

    const int lr = tid >> 1, lc = (tid & 1) * 16;
    const u32 sldoff = (u32)(lr * SASTR + lc) * 2;

    const u32 a_lo = (u32)(((lane & 15) * SASTR + ((lane >> 4) << 3)) * 2);
    const u32 b_lo = (u32)(((((lane >> 4) << 3) + (lane & 7)) * SASTR
                            + (((lane >> 3) & 1) << 3)) * 2);

    const int nk = K / 32;
    auto prefetch = [&](int st, int kt) {
        u32 aB = sbase + st * GSTG;
        size_t aoff = (size_t)(m0 + lr) * K + kt + lc;
        size_t boff = (size_t)(n0 + lr) * K + kt + lc;
        cp16(aB + sldoff,                  Ah_ + aoff);
        cp16(aB + sldoff + 16,             Ah_ + aoff + 8);
        cp16(aB + GTILE*2 + sldoff,        Al_ + aoff);
        cp16(aB + GTILE*2 + sldoff + 16,   Al_ + aoff + 8);
        cp16(aB + 2*GTILE*2 + sldoff,      Bh_ + boff);
        cp16(aB + 2*GTILE*2 + sldoff + 16, Bh_ + boff + 8);
        cp_commit();
    };
    prefetch(0, 0);
    prefetch(1, 32);

    int st = 0;
    for (int kt = 0; kt < nk; kt++) {
        if (kt + 2 < nk) {
            int ps = st + 2; if (ps >= 3) ps -= 3;
            prefetch(ps, (kt + 2) * 32);
        }
        int rem = nk - 1 - kt;
        if (rem >= 2) cp_wait2();
        else if (rem == 1) cp_wait1();
        else cp_wait0();
        __syncthreads();

        const u32 saS = sbase + st * GSTG;
        const u32 sbS = saS + 2 * GTILE * 2;

#pragma unroll
        for (int s = 0; s < 2; s++) {
            u32 af[2][2][4];
#pragma unroll
            for (int hl = 0; hl < 2; hl++)
#pragma unroll
                for (int mf = 0; mf < 2; mf++)
                    ldsm4(af[hl][mf][0], af[hl][mf][1], af[hl][mf][2], af[hl][mf][3],
                          saS + (u32)(hl * GTILE * 2)
                              + (u32)((wm * 32 + mf * 16) * SASTR * 2)
                              + (u32)(s * 32) + a_lo);
#pragma unroll
            for (int np = 0; np < 4; np++) {
                u32 ba = sbS + (u32)((wn * 64 + np * 16) * SASTR * 2)
                             + (u32)(s * 32) + b_lo;
                u32 bh0[2], bh1[2];
                ldsm4(bh0[0], bh0[1], bh1[0], bh1[1], ba);
#pragma unroll
                for (int mf = 0; mf < 2; mf++) {
                    mma_f16(acc[mf][2*np],   af[0][mf], bh0);
                    mma_f16(acc[mf][2*np],   af[1][mf], bh0);
                    mma_f16(acc[mf][2*np+1], af[0][mf], bh1);
                    mma_f16(acc[mf][2*np+1], af[1][mf], bh1);
                }
            }
        }
        __syncthreads();
        if (++st == 3) st = 0;
    }

    // ---- epilogue ----
#pragma unroll
    for (int mf = 0; mf < 2; mf++) {
        int r0 = m0 + wm * 32 + mf * 16 + g;
#pragma unroll
        for (int nf = 0; nf < 8; nf++) {
            int c = n0 + wn * 64 + nf * 8 + 2 * tig;
            float b0 = bias[c], b1 = bias[c + 1];
            float v0 = acc[mf][nf][0] + b0, v1 = acc[mf][nf][1] + b1;
            float v2 = acc[mf][nf][2] + b0, v3 = acc[mf][nf][3] + b1;
            if (MODE == 0) {
                *(float2*)&Cf[(size_t)r0 * N + c]       = make_float2(v0, v1);
                *(float2*)&Cf[(size_t)(r0 + 8) * N + c] = make_float2(v2, v3);
            } else {
                *(u32*)&Ch_[(size_t)r0 * N + c]       = packh(v0, v1);
                *(u32*)&Ch_[(size_t)(r0 + 8) * N + c] = packh(v2, v3);
            }
        }
    }
}

// fused Q/K/V projection: grid.x = 18 (0-15: Q tiles, 16: K, 17: V)
__global__ __launch_bounds__(256, 2)
void gemm_qkv(const u16* __restrict__ xh, const u16* __restrict__ xl,
              const u16* __restrict__ wqh, const u16* __restrict__ wkh,
              const u16* __restrict__ wvh,
              const float* __restrict__ bq, const float* __restrict__ bk,
              const float* __restrict__ bv,
              u16* Qh, u16* Kh, u16* Vh)
{
    extern __shared__ u16 smem[];
    int bx = blockIdx.x, m0 = blockIdx.y * 128;
    if (bx < 16) {
        gemm_core<2>(xh, xl, wqh, bq, nullptr, Qh, DMOD, DMOD, m0, bx * 128, smem);
    } else if (bx == 16) {
        gemm_core<2>(xh, xl, wkh, bk, nullptr, Kh, DH, DMOD, m0, 0, smem);
    } else {
        gemm_core<2>(xh, xl, wvh, bv, nullptr, Vh, DH, DMOD, m0, 0, smem);
    }
}

__global__ __launch_bounds__(256, 2)
void gemm_o(const u16* __restrict__ aoh, const u16* __restrict__ aol,
            const u16* __restrict__ woh,
            const float* __restrict__ bo, float* __restrict__ out)
{
    extern __shared__ u16 smem[];
    gemm_core<0>(aoh, aol, woh, bo, out, nullptr,
                 DMOD, DMOD, blockIdx.y * 128, blockIdx.x * 128, smem);
}

// ============================================================================
// flash attention: 256 thr (8 warps), 128 q-rows/block, 64-key tiles,
// cp.async double-buffered {Kh, Vh}, single-level fp16 MMA (Q,K,V,P all hi),
// scale folded into exp2 constant.
// ============================================================================
#define KSTR   136                      // 272 B row stride, 16B-aligned
#define FTILE  (64 * KSTR)              // 8704 shorts per tile
#define FSTAGE (2 * FTILE)              // Kh, Vh
#define FLASH_SMEM (2 * FSTAGE * 2)     // 69632 B

__global__ __launch_bounds__(256)
void flash_mma(const u16* __restrict__ Qh_, const u16* __restrict__ Kh_,
               const u16* __restrict__ Vh_,
               u16* __restrict__ AOh_, u16* __restrict__ AOl_)
{
    extern __shared__ u16 smem[];
    const u32 sbase = (u32)__cvta_generic_to_shared(smem);
    const float SC = 1.4426950408889634f * 0.08838834764831845f;  // log2e/sqrt(128)

    const int tid = threadIdx.x;
    const int w = tid >> 5, lane = tid & 31;
    const int g = lane >> 2, tig = lane & 3;
    const int b = blockIdx.y >> 4, h = blockIdx.y & 15;
    const int qrow = blockIdx.x * 128 + w * 16 + g;

    const u32 kb_lo = (u32)(((((lane >> 4) << 3) + (lane & 7)) * KSTR
                             + (((lane >> 3) & 1) << 3)) * 2);
    const u32 vb_lo = (u32)((((((lane >> 3) & 1) << 3) + (lane & 7)) * KSTR
                             + ((lane >> 4) << 3)) * 2);

    // ---- prefetch stage 0 ----
    {
        const size_t base = (size_t)(b * SEQ) * DH;
#pragma unroll
        for (int i = tid; i < 1024; i += 256) {
            int r = i >> 4, c = (i & 15) * 8;
            size_t go = base + (size_t)r * DH + c;
            u32 d = sbase + (u32)((r * KSTR + c) * 2);
            cp16(d,           Kh_ + go);
            cp16(d + FTILE*2, Vh_ + go);
        }
        cp_commit();
    }

    // ---- Q fragments resident in registers (hi fp16 only) ----
    u32 qf[8][4];
    {
        size_t qb = (size_t)(b * SEQ + qrow) * DMOD + h * DH;
#pragma unroll
        for (int s = 0; s < 8; s++) {
            int col = s * 16 + 2 * tig;
            qf[s][0] = *(const u32*)(Qh_ + qb + col);
            qf[s][1] = *(const u32*)(Qh_ + qb + 8ull * DMOD + col);
            qf[s][2] = *(const u32*)(Qh_ + qb + col + 8);
            qf[s][3] = *(const u32*)(Qh_ + qb + 8ull * DMOD + col + 8);
        }
    }

    float pacc[16][4];
#pragma unroll
    for (int i = 0; i < 16; i++)
#pragma unroll
        for (int e = 0; e < 4; e++) pacc[i][e] = 0.f;
    float m0 = -1e30f, m1 = -1e30f, l0 = 0.f, l1 = 0.f;

    const int NT = SEQ / 64;
    for (int it = 0; it < NT; it++) {
        if (it + 1 < NT) {
            int st = (it + 1) & 1;
            const size_t base = (size_t)(b * SEQ + (it + 1) * 64) * DH;
            u32 sst = sbase + (u32)(st * FSTAGE * 2);
#pragma unroll
            for (int i = tid; i < 1024; i += 256) {
                int r = i >> 4, c = (i & 15) * 8;
                size_t go = base + (size_t)r * DH + c;
                u32 d = sst + (u32)((r * KSTR + c) * 2);
                cp16(d,           Kh_ + go);
                cp16(d + FTILE*2, Vh_ + go);
            }
            cp_commit();
            cp_wait1();
        } else {
            cp_wait0();
        }
        __syncthreads();

        const u32 sst = sbase + (u32)((it & 1) * FSTAGE * 2);
        const u32 sKh = sst;
        const u32 sVh = sst + FTILE*2;

        // ---- raw scores S = Q K^T (unscaled) ----
        float sa[8][4];
#pragma unroll
        for (int nf = 0; nf < 8; nf++)
#pragma unroll
            for (int e = 0; e < 4; e++) sa[nf][e] = 0.f;

#pragma unroll
        for (int s = 0; s < 8; s++) {
#pragma unroll
            for (int np = 0; np < 4; np++) {
                u32 ba = (u32)(np * 16 * KSTR * 2) + (u32)(s * 32) + kb_lo;
                u32 bh0[2], bh1[2];
                ldsm4(bh0[0], bh0[1], bh1[0], bh1[1], sKh + ba);
                mma_f16(sa[2*np],   qf[s], bh0);
                mma_f16(sa[2*np+1], qf[s], bh1);
            }
        }

        // ---- online softmax (scale folded into SC) ----
        float mx0 = -1e30f, mx1 = -1e30f;
#pragma unroll
        for (int nf = 0; nf < 8; nf++) {
            mx0 = fmaxf(mx0, fmaxf(sa[nf][0], sa[nf][1]));
            mx1 = fmaxf(mx1, fmaxf(sa[nf][2], sa[nf][3]));
        }
        mx0 = fmaxf(mx0, __shfl_xor_sync(0xffffffffu, mx0, 1));
        mx0 = fmaxf(mx0, __shfl_xor_sync(0xffffffffu, mx0, 2));
        mx1 = fmaxf(mx1, __shfl_xor_sync(0xffffffffu, mx1, 1));
        mx1 = fmaxf(mx1, __shfl_xor_sync(0xffffffffu, mx1, 2));
        float nm0 = fmaxf(m0, mx0), nm1 = fmaxf(m1, mx1);
        float corr0 = ex2((m0 - nm0) * SC), corr1 = ex2((m1 - nm1) * SC);
        m0 = nm0; m1 = nm1;
        float nm0s = nm0 * SC, nm1s = nm1 * SC;

        u32 aph[4][4];
        float rs0 = 0.f, rs1 = 0.f;
#pragma unroll
        for (int nf = 0; nf < 8; nf++) {
            float p0 = ex2(fmaf(sa[nf][0], SC, -nm0s));
            float p1 = ex2(fmaf(sa[nf][1], SC, -nm0s));
            float p2 = ex2(fmaf(sa[nf][2], SC, -nm1s));
            float p3 = ex2(fmaf(sa[nf][3], SC, -nm1s));
            rs0 += p0 + p1; rs1 += p2 + p3;
            int ks = nf >> 1, pt = (nf & 1) * 2;
            aph[ks][pt]     = packh(p0, p1);
            aph[ks][pt + 1] = packh(p2, p3);
        }
        rs0 += __shfl_xor_sync(0xffffffffu, rs0, 1);
        rs0 += __shfl_xor_sync(0xffffffffu, rs0, 2);
        rs1 += __shfl_xor_sync(0xffffffffu, rs1, 1);
        rs1 += __shfl_xor_sync(0xffffffffu, rs1, 2);
        l0 = l0 * corr0 + rs0;
        l1 = l1 * corr1 + rs1;
        if (corr0 != 1.f || corr1 != 1.f) {
#pragma unroll
            for (int nf = 0; nf < 16; nf++) {
                pacc[nf][0] *= corr0; pacc[nf][1] *= corr0;
                pacc[nf][2] *= corr1; pacc[nf][3] *= corr1;
            }
        }

        // ---- pacc += P Vh  (V row-major via ldmatrix.trans) ----
#pragma unroll
        for (int ks = 0; ks < 4; ks++) {
#pragma unroll
            for (int np = 0; np < 8; np++) {
                u32 va = (u32)((ks * 16 * KSTR + np * 16) * 2) + vb_lo;
                u32 bh0[2], bh1[2];
                ldsm4t(bh0[0], bh0[1], bh1[0], bh1[1], sVh + va);
                mma_f16(pacc[2*np],   aph[ks], bh0);
                mma_f16(pacc[2*np+1], aph[ks], bh1);
            }
        }
        __syncthreads();
    }

    // ---- epilogue: normalize, split hi/lo fp16, write AO ----
    float inv0 = 1.f / l0, inv1 = 1.f / l1;
    size_t row0 = (size_t)(b * SEQ + qrow) * DMOD + h * DH;
#pragma unroll
    for (int nf = 0; nf < 16; nf++) {
        int c = nf * 8 + 2 * tig;
        float v0 = pacc[nf][0] * inv0, v1 = pacc[nf][1] * inv0;
        float v2 = pacc[nf][2] * inv1, v3 = pacc[nf][3] * inv1;
        u32 hp0 = packh(v0, v1), hp1 = packh(v2, v3);
        __half2 a = *(__half2*)&hp0, bb = *(__half2*)&hp1;
        *(u32*)(AOh_ + row0 + c)             = hp0;
        *(u32*)(AOh_ + row0 + 8ull*DMOD + c) = hp1;
        *(u32*)(AOl_ + row0 + c) =
            packh(v0 - __low2float(a), v1 - __high2float(a));
        *(u32*)(AOl_ + row0 + 8ull*DMOD + c) =
            packh(v2 - __low2float(bb), v3 - __high2float(bb));
    }
}

// ---------------- launch ----------------
extern "C" void kernel_launch(void* const* d_in, const int* in_sizes, int n_in,
                              void* d_out, int out_size)
{
    (void)in_sizes; (void)n_in; (void)out_size;
    const float* x  = (const float*)d_in[0];
    const float* Wq = (const float*)d_in[1];
    const float* bq = (const float*)d_in[2];
    const float* Wk = (const float*)d_in[3];
    const float* bk = (const float*)d_in[4];
    const float* Wv = (const float*)d_in[5];
    const float* bv = (const float*)d_in[6];
    const float* Wo = (const float*)d_in[7];
    const float* bo = (const float*)d_in[8];
    float* out = (float*)d_out;

    void *xh,*xl,*wqh,*wkh,*wvh,*woh;
    void *qh,*kh,*vh,*aoh,*aol;
    cudaGetSymbolAddress(&xh,  g_xh);   cudaGetSymbolAddress(&xl,  g_xl);
    cudaGetSymbolAddress(&wqh, g_WqTh);
    cudaGetSymbolAddress(&wkh, g_WkTh);
    cudaGetSymbolAddress(&wvh, g_WvTh);
    cudaGetSymbolAddress(&woh, g_WoTh);
    cudaGetSymbolAddress(&qh,  g_Qh);
    cudaGetSymbolAddress(&kh,  g_Kh);
    cudaGetSymbolAddress(&vh,  g_Vh);
    cudaGetSymbolAddress(&aoh, g_AOh);  cudaGetSymbolAddress(&aol, g_AOl);

    cudaFuncSetAttribute(gemm_qkv,
        cudaFuncAttributeMaxDynamicSharedMemorySize, GEMM_SMEM);
    cudaFuncSetAttribute(gemm_o,
        cudaFuncAttributeMaxDynamicSharedMemorySize, GEMM_SMEM);
    cudaFuncSetAttribute(flash_mma,
        cudaFuncAttributeMaxDynamicSharedMemorySize, FLASH_SMEM);

    // 0) split inputs (weights: hi only)
    int n4 = MTOK * DMOD / 4;
    split_f32<<<(n4 + 255) / 256, 256>>>(x, (u16*)xh, (u16*)xl, n4);
    wtsplit<<<dim3(DMOD/32, DMOD/32), dim3(32, 8)>>>(Wq, (u16*)wqh, DMOD, DMOD);
    wtsplit<<<dim3(DH/32,   DMOD/32), dim3(32, 8)>>>(Wk, (u16*)wkh, DMOD, DH);
    wtsplit<<<dim3(DH/32,   DMOD/32), dim3(32, 8)>>>(Wv, (u16*)wvh, DMOD, DH);
    wtsplit<<<dim3(DMOD/32, DMOD/32), dim3(32, 8)>>>(Wo, (u16*)woh, DMOD, DMOD);

    // 1) fused Q/K/V projections (all hi-only outputs)
    gemm_qkv<<<dim3(18, MTOK/128), 256, GEMM_SMEM>>>(
        (u16*)xh, (u16*)xl, (u16*)wqh, (u16*)wkh, (u16*)wvh, bq, bk, bv,
        (u16*)qh, (u16*)kh, (u16*)vh);

    // 2) flash attention (single-level fp16 inputs)
    flash_mma<<<dim3(SEQ/128, NB*NH), 256, FLASH_SMEM>>>(
        (u16*)qh, (u16*)kh, (u16*)vh, (u16*)aoh, (u16*)aol);

    // 3) out = AO @ Wo + bo (AO hi/lo 2-term, fp32 out)
    gemm_o<<<dim3(DMOD/128, MTOK/128), 256, GEMM_SMEM>>>(
        (u16*)aoh, (u16*)aol, (u16*)woh, bo, out);
}

// round 15
// speedup vs baseline: 2.7090x; 1.2086x over previous
#include <cuda_runtime.h>
#include <cuda_fp16.h>

// ---------------- problem constants ----------------
#define MTOK  4096
#define DMOD  2048
#define NH    16
#define DH    128
#define SEQ   2048
#define NB    2

typedef unsigned int u32;
typedef unsigned short u16;

// ---------------- scratch (device globals; 16B-aligned for cp.async) ------
__device__ __align__(256) u16 g_xh [MTOK*DMOD], g_xl [MTOK*DMOD];
__device__ __align__(256) u16 g_WqTh[DMOD*DMOD];
__device__ __align__(256) u16 g_WkTh[DH*DMOD];
__device__ __align__(256) u16 g_WvTh[DH*DMOD];
__device__ __align__(256) u16 g_WoTh[DMOD*DMOD];
__device__ __align__(256) u16 g_Qh [MTOK*DMOD];
__device__ __align__(256) u16 g_Kh [MTOK*DH];
__device__ __align__(256) u16 g_Vh [MTOK*DH];
__device__ __align__(256) u16 g_AOh[MTOK*DMOD];

// ---------------- PTX helpers ----------------
__device__ __forceinline__ void mma_f16(float* c, const u32* a, const u32* b) {
    asm("mma.sync.aligned.m16n8k16.row.col.f32.f16.f16.f32 "
        "{%0,%1,%2,%3},{%4,%5,%6,%7},{%8,%9},{%0,%1,%2,%3};"
        : "+f"(c[0]), "+f"(c[1]), "+f"(c[2]), "+f"(c[3])
        : "r"(a[0]), "r"(a[1]), "r"(a[2]), "r"(a[3]), "r"(b[0]), "r"(b[1]));
}
__device__ __forceinline__ void ldsm4(u32& r0, u32& r1, u32& r2, u32& r3, u32 a) {
    asm volatile("ldmatrix.sync.aligned.m8n8.x4.shared.b16 {%0,%1,%2,%3},[%4];"
                 : "=r"(r0), "=r"(r1), "=r"(r2), "=r"(r3) : "r"(a));
}
__device__ __forceinline__ void ldsm4t(u32& r0, u32& r1, u32& r2, u32& r3, u32 a) {
    asm volatile("ldmatrix.sync.aligned.m8n8.x4.trans.shared.b16 {%0,%1,%2,%3},[%4];"
                 : "=r"(r0), "=r"(r1), "=r"(r2), "=r"(r3) : "r"(a));
}
__device__ __forceinline__ void cp16(u32 dst, const void* src) {
    asm volatile("cp.async.cg.shared.global [%0], [%1], 16;" :: "r"(dst), "l"(src));
}
__device__ __forceinline__ void cp_commit() { asm volatile("cp.async.commit_group;"); }
__device__ __forceinline__ void cp_wait0()  { asm volatile("cp.async.wait_group 0;"); }
__device__ __forceinline__ void cp_wait1()  { asm volatile("cp.async.wait_group 1;"); }
__device__ __forceinline__ void cp_wait2()  { asm volatile("cp.async.wait_group 2;"); }

__device__ __forceinline__ u32 packh(float a, float b) {   // a -> low 16 bits
    __half2 t = __floats2half2_rn(a, b);
    return *reinterpret_cast<u32*>(&t);
}
__device__ __forceinline__ float ex2(float x) {
    float y; asm("ex2.approx.ftz.f32 %0, %1;" : "=f"(y) : "f"(x)); return y;
}

// ---------------- converters ----------------
// x fp32 -> hi/lo fp16
__global__ void split_f32(const float* __restrict__ in,
                          u16* __restrict__ h, u16* __restrict__ l, int n4) {
    int i = blockIdx.x * blockDim.x + threadIdx.x;
    if (i >= n4) return;
    float4 v = ((const float4*)in)[i];
    u32 h0 = packh(v.x, v.y);
    u32 h1 = packh(v.z, v.w);
    __half2 a = *(__half2*)&h0, b = *(__half2*)&h1;
    ((u32*)h)[2*i]   = h0;
    ((u32*)h)[2*i+1] = h1;
    ((u32*)l)[2*i]   = packh(v.x - __low2float(a), v.y - __high2float(a));
    ((u32*)l)[2*i+1] = packh(v.z - __low2float(b), v.w - __high2float(b));
}

// W[K][N] fp32 -> WT[N][K] fp16 (hi only)
__global__ void wtsplit(const float* __restrict__ W,
                        u16* __restrict__ Th, int K, int N) {
    __shared__ float t[32][33];
    int nt = blockIdx.x * 32, kt = blockIdx.y * 32;
    int tx = threadIdx.x, ty = threadIdx.y;
#pragma unroll
    for (int j = 0; j < 4; j++)
        t[ty + 8*j][tx] = W[(size_t)(kt + ty + 8*j) * N + nt + tx];
    __syncthreads();
#pragma unroll
    for (int j = 0; j < 4; j++) {
        float v = t[tx][ty + 8*j];
        size_t idx = (size_t)(nt + ty + 8*j) * K + kt + tx;
        ((__half*)Th)[idx] = __float2half_rn(v);
    }
}

// ============================================================================
// fp16 GEMM: C = (Ah [+Al]) @ Bh^T + bias. 128x128 tile, BK=32, 256 thr,
// cp.async 3-stage pipeline, ldmatrix. 2 CTAs/SM.
// MODE 0: fp32 out.  MODE 2: fp16 hi out.   TERMS: 1 or 2 A-terms.
// ============================================================================
#define SASTR 40                     // padded smem row stride (shorts) = 80 B
#define GTILE (128 * SASTR)          // 5120 shorts per tile
#define GSTG  (3 * GTILE * 2)        // stage bytes: Ah + Al + Bh = 30720
#define GEMM_SMEM (3 * GSTG)         // 3 stages = 92160 B

template<int MODE, int TERMS>
__device__ __forceinline__ void gemm_core(
    const u16* __restrict__ Ah_, const u16* __restrict__ Al_,
    const u16* __restrict__ Bh_,
    const float* __restrict__ bias,
    float* __restrict__ Cf, u16* __restrict__ Ch_,
    int N, int K, int m0, int n0, u16* smem)
{
    const int tid  = threadIdx.x;
    const int warp = tid >> 5, lane = tid & 31;
    const int g = lane >> 2, tig = lane & 3;
    const int wm = warp >> 1, wn = warp & 1;

    const u32 sbase = (u32)__cvta_generic_to_shared(smem);

    float acc[2][8][4];
#pragma unroll
    for (int i = 0; i < 2; i++)
#pragma unroll
        for (int j = 0; j < 8; j++)
#pragma unroll
            for (int e = 0; e < 4; e++) acc[i][j][e] = 0.f;

    const int lr = tid >> 1, lc = (tid & 1) * 16;
    const u32 sldoff = (u32)(lr * SASTR + lc) * 2;

    const u32 a_lo = (u32)(((lane & 15) * SASTR + ((lane >> 4) << 3)) * 2);
    const u32 b_lo = (u32)(((((lane >> 4) << 3) + (lane & 7)) * SASTR
                            + (((lane >> 3) & 1) << 3)) * 2);

    const int nk = K / 32;
    auto prefetch = [&](int st, int kt) {
        u32 aB = sbase + st * GSTG;
        size_t aoff = (size_t)(m0 + lr) * K + kt + lc;
        size_t boff = (size_t)(n0 + lr) * K + kt + lc;
        cp16(aB + sldoff,                  Ah_ + aoff);
        cp16(aB + sldoff + 16,             Ah_ + aoff + 8);
        if (TERMS == 2) {
            cp16(aB + GTILE*2 + sldoff,        Al_ + aoff);
            cp16(aB + GTILE*2 + sldoff + 16,   Al_ + aoff + 8);
        }
        cp16(aB + 2*GTILE*2 + sldoff,      Bh_ + boff);
        cp16(aB + 2*GTILE*2 + sldoff + 16, Bh_ + boff + 8);
        cp_commit();
    };
    prefetch(0, 0);
    prefetch(1, 32);

    int st = 0;
    for (int kt = 0; kt < nk; kt++) {
        if (kt + 2 < nk) {
            int ps = st + 2; if (ps >= 3) ps -= 3;
            prefetch(ps, (kt + 2) * 32);
        }
        int rem = nk - 1 - kt;
        if (rem >= 2) cp_wait2();
        else if (rem == 1) cp_wait1();
        else cp_wait0();
        __syncthreads();

        const u32 saS = sbase + st * GSTG;
        const u32 sbS = saS + 2 * GTILE * 2;

#pragma unroll
        for (int s = 0; s < 2; s++) {
            u32 af[TERMS][2][4];
#pragma unroll
            for (int hl = 0; hl < TERMS; hl++)
#pragma unroll
                for (int mf = 0; mf < 2; mf++)
                    ldsm4(af[hl][mf][0], af[hl][mf][1], af[hl][mf][2], af[hl][mf][3],
                          saS + (u32)(hl * GTILE * 2)
                              + (u32)((wm * 32 + mf * 16) * SASTR * 2)
                              + (u32)(s * 32) + a_lo);
#pragma unroll
            for (int np = 0; np < 4; np++) {
                u32 ba = sbS + (u32)((wn * 64 + np * 16) * SASTR * 2)
                             + (u32)(s * 32) + b_lo;
                u32 bh0[2], bh1[2];
                ldsm4(bh0[0], bh0[1], bh1[0], bh1[1], ba);
#pragma unroll
                for (int mf = 0; mf < 2; mf++) {
                    mma_f16(acc[mf][2*np],   af[0][mf], bh0);
                    mma_f16(acc[mf][2*np+1], af[0][mf], bh1);
                    if (TERMS == 2) {
                        mma_f16(acc[mf][2*np],   af[1][mf], bh0);
                        mma_f16(acc[mf][2*np+1], af[1][mf], bh1);
                    }
                }
            }
        }
        __syncthreads();
        if (++st == 3) st = 0;
    }

    // ---- epilogue ----
#pragma unroll
    for (int mf = 0; mf < 2; mf++) {
        int r0 = m0 + wm * 32 + mf * 16 + g;
#pragma unroll
        for (int nf = 0; nf < 8; nf++) {
            int c = n0 + wn * 64 + nf * 8 + 2 * tig;
            float b0 = bias[c], b1 = bias[c + 1];
            float v0 = acc[mf][nf][0] + b0, v1 = acc[mf][nf][1] + b1;
            float v2 = acc[mf][nf][2] + b0, v3 = acc[mf][nf][3] + b1;
            if (MODE == 0) {
                *(float2*)&Cf[(size_t)r0 * N + c]       = make_float2(v0, v1);
                *(float2*)&Cf[(size_t)(r0 + 8) * N + c] = make_float2(v2, v3);
            } else {
                *(u32*)&Ch_[(size_t)r0 * N + c]       = packh(v0, v1);
                *(u32*)&Ch_[(size_t)(r0 + 8) * N + c] = packh(v2, v3);
            }
        }
    }
}

// fused Q/K/V projection: grid.x = 18 (0-15: Q tiles 1-term, 16: K, 17: V 2-term)
__global__ __launch_bounds__(256, 2)
void gemm_qkv(const u16* __restrict__ xh, const u16* __restrict__ xl,
              const u16* __restrict__ wqh, const u16* __restrict__ wkh,
              const u16* __restrict__ wvh,
              const float* __restrict__ bq, const float* __restrict__ bk,
              const float* __restrict__ bv,
              u16* Qh, u16* Kh, u16* Vh)
{
    extern __shared__ u16 smem[];
    int bx = blockIdx.x, m0 = blockIdx.y * 128;
    if (bx < 16) {
        gemm_core<2, 1>(xh, xl, wqh, bq, nullptr, Qh, DMOD, DMOD, m0, bx * 128, smem);
    } else if (bx == 16) {
        gemm_core<2, 2>(xh, xl, wkh, bk, nullptr, Kh, DH, DMOD, m0, 0, smem);
    } else {
        gemm_core<2, 2>(xh, xl, wvh, bv, nullptr, Vh, DH, DMOD, m0, 0, smem);
    }
}

__global__ __launch_bounds__(256, 2)
void gemm_o(const u16* __restrict__ aoh,
            const u16* __restrict__ woh,
            const float* __restrict__ bo, float* __restrict__ out)
{
    extern __shared__ u16 smem[];
    gemm_core<0, 1>(aoh, nullptr, woh, bo, out, nullptr,
                    DMOD, DMOD, blockIdx.y * 128, blockIdx.x * 128, smem);
}

// ============================================================================
// flash attention: 256 thr (8 warps), 128 q-rows/block, 64-key tiles,
// cp.async double-buffered {Kh, Vh}, single-level fp16 MMA,
// scale folded into exp2 constant. AO out: fp16 hi only.
// ============================================================================
#define KSTR   136                      // 272 B row stride, 16B-aligned
#define FTILE  (64 * KSTR)              // 8704 shorts per tile
#define FSTAGE (2 * FTILE)              // Kh, Vh
#define FLASH_SMEM (2 * FSTAGE * 2)     // 69632 B

__global__ __launch_bounds__(256)
void flash_mma(const u16* __restrict__ Qh_, const u16* __restrict__ Kh_,
               const u16* __restrict__ Vh_,
               u16* __restrict__ AOh_)
{
    extern __shared__ u16 smem[];
    const u32 sbase = (u32)__cvta_generic_to_shared(smem);
    const float SC = 1.4426950408889634f * 0.08838834764831845f;  // log2e/sqrt(128)

    const int tid = threadIdx.x;
    const int w = tid >> 5, lane = tid & 31;
    const int g = lane >> 2, tig = lane & 3;
    const int b = blockIdx.y >> 4, h = blockIdx.y & 15;
    const int qrow = blockIdx.x * 128 + w * 16 + g;

    const u32 kb_lo = (u32)(((((lane >> 4) << 3) + (lane & 7)) * KSTR
                             + (((lane >> 3) & 1) << 3)) * 2);
    const u32 vb_lo = (u32)((((((lane >> 3) & 1) << 3) + (lane & 7)) * KSTR
                             + ((lane >> 4) << 3)) * 2);

    // ---- prefetch stage 0 ----
    {
        const size_t base = (size_t)(b * SEQ) * DH;
#pragma unroll
        for (int i = tid; i < 1024; i += 256) {
            int r = i >> 4, c = (i & 15) * 8;
            size_t go = base + (size_t)r * DH + c;
            u32 d = sbase + (u32)((r * KSTR + c) * 2);
            cp16(d,           Kh_ + go);
            cp16(d + FTILE*2, Vh_ + go);
        }
        cp_commit();
    }

    // ---- Q fragments resident in registers (hi fp16) ----
    u32 qf[8][4];
    {
        size_t qb = (size_t)(b * SEQ + qrow) * DMOD + h * DH;
#pragma unroll
        for (int s = 0; s < 8; s++) {
            int col = s * 16 + 2 * tig;
            qf[s][0] = *(const u32*)(Qh_ + qb + col);
            qf[s][1] = *(const u32*)(Qh_ + qb + 8ull * DMOD + col);
            qf[s][2] = *(const u32*)(Qh_ + qb + col + 8);
            qf[s][3] = *(const u32*)(Qh_ + qb + 8ull * DMOD + col + 8);
        }
    }

    float pacc[16][4];
#pragma unroll
    for (int i = 0; i < 16; i++)
#pragma unroll
        for (int e = 0; e < 4; e++) pacc[i][e] = 0.f;
    float m0 = -1e30f, m1 = -1e30f, l0 = 0.f, l1 = 0.f;

    const int NT = SEQ / 64;
    for (int it = 0; it < NT; it++) {
        if (it + 1 < NT) {
            int st = (it + 1) & 1;
            const size_t base = (size_t)(b * SEQ + (it + 1) * 64) * DH;
            u32 sst = sbase + (u32)(st * FSTAGE * 2);
#pragma unroll
            for (int i = tid; i < 1024; i += 256) {
                int r = i >> 4, c = (i & 15) * 8;
                size_t go = base + (size_t)r * DH + c;
                u32 d = sst + (u32)((r * KSTR + c) * 2);
                cp16(d,           Kh_ + go);
                cp16(d + FTILE*2, Vh_ + go);
            }
            cp_commit();
            cp_wait1();
        } else {
            cp_wait0();
        }
        __syncthreads();

        const u32 sst = sbase + (u32)((it & 1) * FSTAGE * 2);
        const u32 sKh = sst;
        const u32 sVh = sst + FTILE*2;

        // ---- raw scores S = Q K^T (unscaled) ----
        float sa[8][4];
#pragma unroll
        for (int nf = 0; nf < 8; nf++)
#pragma unroll
            for (int e = 0; e < 4; e++) sa[nf][e] = 0.f;

#pragma unroll
        for (int s = 0; s < 8; s++) {
#pragma unroll
            for (int np = 0; np < 4; np++) {
                u32 ba = (u32)(np * 16 * KSTR * 2) + (u32)(s * 32) + kb_lo;
                u32 bh0[2], bh1[2];
                ldsm4(bh0[0], bh0[1], bh1[0], bh1[1], sKh + ba);
                mma_f16(sa[2*np],   qf[s], bh0);
                mma_f16(sa[2*np+1], qf[s], bh1);
            }
        }

        // ---- online softmax (scale folded into SC) ----
        float mx0 = -1e30f, mx1 = -1e30f;
#pragma unroll
        for (int nf = 0; nf < 8; nf++) {
            mx0 = fmaxf(mx0, fmaxf(sa[nf][0], sa[nf][1]));
            mx1 = fmaxf(mx1, fmaxf(sa[nf][2], sa[nf][3]));
        }
        mx0 = fmaxf(mx0, __shfl_xor_sync(0xffffffffu, mx0, 1));
        mx0 = fmaxf(mx0, __shfl_xor_sync(0xffffffffu, mx0, 2));
        mx1 = fmaxf(mx1, __shfl_xor_sync(0xffffffffu, mx1, 1));
        mx1 = fmaxf(mx1, __shfl_xor_sync(0xffffffffu, mx1, 2));
        float nm0 = fmaxf(m0, mx0), nm1 = fmaxf(m1, mx1);
        float corr0 = ex2((m0 - nm0) * SC), corr1 = ex2((m1 - nm1) * SC);
        m0 = nm0; m1 = nm1;
        float nm0s = nm0 * SC, nm1s = nm1 * SC;

        u32 aph[4][4];
        float rs0 = 0.f, rs1 = 0.f;
#pragma unroll
        for (int nf = 0; nf < 8; nf++) {
            float p0 = ex2(fmaf(sa[nf][0], SC, -nm0s));
            float p1 = ex2(fmaf(sa[nf][1], SC, -nm0s));
            float p2 = ex2(fmaf(sa[nf][2], SC, -nm1s));
            float p3 = ex2(fmaf(sa[nf][3], SC, -nm1s));
            rs0 += p0 + p1; rs1 += p2 + p3;
            int ks = nf >> 1, pt = (nf & 1) * 2;
            aph[ks][pt]     = packh(p0, p1);
            aph[ks][pt + 1] = packh(p2, p3);
        }
        rs0 += __shfl_xor_sync(0xffffffffu, rs0, 1);
        rs0 += __shfl_xor_sync(0xffffffffu, rs0, 2);
        rs1 += __shfl_xor_sync(0xffffffffu, rs1, 1);
        rs1 += __shfl_xor_sync(0xffffffffu, rs1, 2);
        l0 = l0 * corr0 + rs0;
        l1 = l1 * corr1 + rs1;
        if (corr0 != 1.f || corr1 != 1.f) {
#pragma unroll
            for (int nf = 0; nf < 16; nf++) {
                pacc[nf][0] *= corr0; pacc[nf][1] *= corr0;
                pacc[nf][2] *= corr1; pacc[nf][3] *= corr1;
            }
        }

        // ---- pacc += P Vh (V row-major via ldmatrix.trans) ----
#pragma unroll
        for (int ks = 0; ks < 4; ks++) {
#pragma unroll
            for (int np = 0; np < 8; np++) {
                u32 va = (u32)((ks * 16 * KSTR + np * 16) * 2) + vb_lo;
                u32 bh0[2], bh1[2];
                ldsm4t(bh0[0], bh0[1], bh1[0], bh1[1], sVh + va);
                mma_f16(pacc[2*np],   aph[ks], bh0);
                mma_f16(pacc[2*np+1], aph[ks], bh1);
            }
        }
        __syncthreads();
    }

    // ---- epilogue: normalize, write AO (fp16 hi only) ----
    float inv0 = 1.f / l0, inv1 = 1.f / l1;
    size_t row0 = (size_t)(b * SEQ + qrow) * DMOD + h * DH;
#pragma unroll
    for (int nf = 0; nf < 16; nf++) {
        int c = nf * 8 + 2 * tig;
        *(u32*)(AOh_ + row0 + c) =
            packh(pacc[nf][0] * inv0, pacc[nf][1] * inv0);
        *(u32*)(AOh_ + row0 + 8ull*DMOD + c) =
            packh(pacc[nf][2] * inv1, pacc[nf][3] * inv1);
    }
}

// ---------------- launch ----------------
extern "C" void kernel_launch(void* const* d_in, const int* in_sizes, int n_in,
                              void* d_out, int out_size)
{
    (void)in_sizes; (void)n_in; (void)out_size;
    const float* x  = (const float*)d_in[0];
    const float* Wq = (const float*)d_in[1];
    const float* bq = (const float*)d_in[2];
    const float* Wk = (const float*)d_in[3];
    const float* bk = (const float*)d_in[4];
    const float* Wv = (const float*)d_in[5];
    const float* bv = (const float*)d_in[6];
    const float* Wo = (const float*)d_in[7];
    const float* bo = (const float*)d_in[8];
    float* out = (float*)d_out;

    void *xh,*xl,*wqh,*wkh,*wvh,*woh;
    void *qh,*kh,*vh,*aoh;
    cudaGetSymbolAddress(&xh,  g_xh);   cudaGetSymbolAddress(&xl,  g_xl);
    cudaGetSymbolAddress(&wqh, g_WqTh);
    cudaGetSymbolAddress(&wkh, g_WkTh);
    cudaGetSymbolAddress(&wvh, g_WvTh);
    cudaGetSymbolAddress(&woh, g_WoTh);
    cudaGetSymbolAddress(&qh,  g_Qh);
    cudaGetSymbolAddress(&kh,  g_Kh);
    cudaGetSymbolAddress(&vh,  g_Vh);
    cudaGetSymbolAddress(&aoh, g_AOh);

    cudaFuncSetAttribute(gemm_qkv,
        cudaFuncAttributeMaxDynamicSharedMemorySize, GEMM_SMEM);
    cudaFuncSetAttribute(gemm_o,
        cudaFuncAttributeMaxDynamicSharedMemorySize, GEMM_SMEM);
    cudaFuncSetAttribute(flash_mma,
        cudaFuncAttributeMaxDynamicSharedMemorySize, FLASH_SMEM);

    // 0) split inputs (weights: hi only; x: hi/lo for K,V 2-term)
    int n4 = MTOK * DMOD / 4;
    split_f32<<<(n4 + 255) / 256, 256>>>(x, (u16*)xh, (u16*)xl, n4);
    wtsplit<<<dim3(DMOD/32, DMOD/32), dim3(32, 8)>>>(Wq, (u16*)wqh, DMOD, DMOD);
    wtsplit<<<dim3(DH/32,   DMOD/32), dim3(32, 8)>>>(Wk, (u16*)wkh, DMOD, DH);
    wtsplit<<<dim3(DH/32,   DMOD/32), dim3(32, 8)>>>(Wv, (u16*)wvh, DMOD, DH);
    wtsplit<<<dim3(DMOD/32, DMOD/32), dim3(32, 8)>>>(Wo, (u16*)woh, DMOD, DMOD);

    // 1) fused Q/K/V projections (Q 1-term; K,V 2-term)
    gemm_qkv<<<dim3(18, MTOK/128), 256, GEMM_SMEM>>>(
        (u16*)xh, (u16*)xl, (u16*)wqh, (u16*)wkh, (u16*)wvh, bq, bk, bv,
        (u16*)qh, (u16*)kh, (u16*)vh);

    // 2) flash attention
    flash_mma<<<dim3(SEQ/128, NB*NH), 256, FLASH_SMEM>>>(
        (u16*)qh, (u16*)kh, (u16*)vh, (u16*)aoh);

    // 3) out = AO @ Wo + bo (1-term, fp32 out)
    gemm_o<<<dim3(DMOD/128, MTOK/128), 256, GEMM_SMEM>>>(
        (u16*)aoh, (u16*)woh, bo, out);
}